// round 2
// baseline (speedup 1.0000x reference)
#include <cuda_runtime.h>
#include <stdint.h>

#define N_NODES 20000
#define NPAD    20096           // 157 * 128
#define HID     256
#define E_EDGES 640000
#define NH      (N_NODES * HID) // 5,120,000

// ---------------- scratch (device globals; no allocation) ----------------
__device__ int   g_is64;
__device__ int   g_deg[N_NODES];
__device__ int   g_cursor[N_NODES];
__device__ int   g_rowptr[N_NODES + 1];
__device__ int   g_srcA[E_EDGES];
__device__ int   g_dstA[E_EDGES];
__device__ int2  g_csr[E_EDGES];        // (src, bitcast(dinv[src]))
__device__ float g_dinv[N_NODES];
__device__ float g_aggx[N_NODES];
__device__ float g_h[NPAD * HID];       // padded rows stay zero forever
__device__ float g_t[NPAD * HID];

// ---------------- threefry2x32 (JAX-exact) ----------------
__host__ __device__ __forceinline__ void threefry2x32(
    uint32_t k0, uint32_t k1, uint32_t x0, uint32_t x1,
    uint32_t* o0, uint32_t* o1)
{
    uint32_t ks2 = k0 ^ k1 ^ 0x1BD11BDAu;
    x0 += k0; x1 += k1;
#define TF_R(r) { x0 += x1; x1 = (x1 << (r)) | (x1 >> (32 - (r))); x1 ^= x0; }
    TF_R(13) TF_R(15) TF_R(26) TF_R(6)
    x0 += k1; x1 += ks2 + 1u;
    TF_R(17) TF_R(29) TF_R(16) TF_R(24)
    x0 += ks2; x1 += k0 + 2u;
    TF_R(13) TF_R(15) TF_R(26) TF_R(6)
    x0 += k0; x1 += k1 + 3u;
    TF_R(17) TF_R(29) TF_R(16) TF_R(24)
    x0 += k1; x1 += ks2 + 4u;
    TF_R(13) TF_R(15) TF_R(26) TF_R(6)
    x0 += ks2; x1 += k0 + 5u;
#undef TF_R
    *o0 = x0; *o1 = x1;
}

// dropout mask, JAX partitionable-threefry semantics:
//   bits32[e] = o0 ^ o1   at counter (hi=0, lo=e)        (bits1 ^ bits2 in JAX)
//   uniform   = ((bits>>9)|0x3f800000).view(f32) - 1
//   keep <=> uniform < 0.5 <=> bit31(bits) == 0 ; kept values scaled by 1/(1-p)=2
__device__ __forceinline__ float apply_dropout(float v, uint32_t k0, uint32_t k1, uint32_t e)
{
    uint32_t o0, o1;
    threefry2x32(k0, k1, 0u, e, &o0, &o1);
    return ((o0 ^ o1) & 0x80000000u) ? 0.0f : 2.0f * v;
}

// ---------------- preprocessing ----------------
__global__ void detect_kernel(const unsigned int* __restrict__ w)
{
    // int64 little-endian: high 32-bit words (odd indices) are all zero
    int z = 1;
    for (int k = 0; k < 64; ++k)
        if (w[2 * k + 1] != 0u) { z = 0; break; }
    g_is64 = z;
}

__global__ void init_kernel()
{
    int i = blockIdx.x * blockDim.x + threadIdx.x;
    if (i < N_NODES) { g_deg[i] = 0; g_cursor[i] = 0; }
}

__global__ void convert_kernel(const void* __restrict__ ei)
{
    int e = blockIdx.x * blockDim.x + threadIdx.x;
    if (e >= E_EDGES) return;
    int s, d;
    if (g_is64) {
        const long long* p = (const long long*)ei;
        s = (int)p[e]; d = (int)p[E_EDGES + e];
    } else {
        const int* p = (const int*)ei;
        s = p[e]; d = p[E_EDGES + e];
    }
    g_srcA[e] = s; g_dstA[e] = d;
    atomicAdd(&g_deg[d], 1);
}

__global__ void scan_kernel()
{
    __shared__ int s[1024];
    __shared__ int carry;
    if (threadIdx.x == 0) carry = 0;
    __syncthreads();
    for (int base = 0; base < N_NODES; base += 1024) {
        int i = base + threadIdx.x;
        int v = (i < N_NODES) ? g_deg[i] : 0;
        if (i < N_NODES) g_dinv[i] = rsqrtf((float)(v + 1));  // +1 self loop
        int orig = v;
        s[threadIdx.x] = v;
        __syncthreads();
        for (int d = 1; d < 1024; d <<= 1) {
            int add = (threadIdx.x >= d) ? s[threadIdx.x - d] : 0;
            __syncthreads();
            s[threadIdx.x] += add;
            __syncthreads();
        }
        if (i < N_NODES) g_rowptr[i] = carry + s[threadIdx.x] - orig;
        __syncthreads();
        if (threadIdx.x == 1023) carry += s[1023];
        __syncthreads();
    }
    if (threadIdx.x == 0) g_rowptr[N_NODES] = carry;
}

__global__ void scatter_kernel()
{
    int e = blockIdx.x * blockDim.x + threadIdx.x;
    if (e >= E_EDGES) return;
    int d = g_dstA[e], s = g_srcA[e];
    int pos = g_rowptr[d] + atomicAdd(&g_cursor[d], 1);
    g_csr[pos] = make_int2(s, __float_as_int(g_dinv[s]));
}

// ---------------- layer 1 (Fin = 1 rewrite) ----------------
__global__ void aggx_kernel(const float* __restrict__ x)
{
    int lane = threadIdx.x & 31;
    int node = (blockIdx.x * blockDim.x + threadIdx.x) >> 5;
    if (node >= N_NODES) return;
    int s = g_rowptr[node], e_end = g_rowptr[node + 1];
    float sum = 0.0f;
    for (int e = s + lane; e < e_end; e += 32) {
        int2 sw = g_csr[e];
        sum = fmaf(__int_as_float(sw.y), __ldg(x + sw.x), sum);
    }
#pragma unroll
    for (int d = 16; d; d >>= 1) sum += __shfl_xor_sync(0xffffffffu, sum, d);
    if (lane == 0) {
        float di = g_dinv[node];
        g_aggx[node] = di * fmaf(di, __ldg(x + node), sum);
    }
}

__global__ void expand_l1_kernel(const float* __restrict__ W0,
                                 const float* __restrict__ b0,
                                 uint32_t k0, uint32_t k1)
{
    int e = blockIdx.x * blockDim.x + threadIdx.x;
    if (e >= NH) return;
    int i = e >> 8, j = e & 255;
    float v = fmaxf(fmaf(g_aggx[i], W0[j], b0[j]), 0.0f);
    g_h[e] = apply_dropout(v, k0, k1, (uint32_t)e);
}

// ---------------- GEMM: g_t = g_h @ B   (NPAD x 256) x (256 x 256) ----------------
__global__ void gemm_kernel(const float* __restrict__ B)
{
    __shared__ float As[8][132];
    __shared__ float Bs[8][132];
    int tid = threadIdx.x;
    int m0 = blockIdx.x * 128;
    int n0 = blockIdx.y * 128;
    int tm = (tid >> 4) * 4;   // rows  {tm..tm+3} and {64+tm..}
    int tn = (tid & 15) * 4;   // cols  {tn..tn+3} and {64+tn..}

    float acc[8][8];
#pragma unroll
    for (int i = 0; i < 8; ++i)
#pragma unroll
        for (int j = 0; j < 8; ++j) acc[i][j] = 0.0f;

    int arow = tid >> 1;
    int aseg = (tid & 1) * 4;
    int brow = tid >> 5;
    int bseg = (tid & 31) * 4;
    const float* Ag = g_h + (m0 + arow) * HID + aseg;
    const float* Bg = B + brow * HID + n0 + bseg;

    for (int kt = 0; kt < 256; kt += 8) {
        float4 av = *(const float4*)(Ag + kt);
        float4 bv = *(const float4*)(Bg + kt * HID);
        __syncthreads();
        As[aseg + 0][arow] = av.x;
        As[aseg + 1][arow] = av.y;
        As[aseg + 2][arow] = av.z;
        As[aseg + 3][arow] = av.w;
        *(float4*)&Bs[brow][bseg] = bv;
        __syncthreads();
#pragma unroll
        for (int k = 0; k < 8; ++k) {
            float a[8], b[8];
            *(float4*)(a)     = *(const float4*)&As[k][tm];
            *(float4*)(a + 4) = *(const float4*)&As[k][64 + tm];
            *(float4*)(b)     = *(const float4*)&Bs[k][tn];
            *(float4*)(b + 4) = *(const float4*)&Bs[k][64 + tn];
#pragma unroll
            for (int i = 0; i < 8; ++i)
#pragma unroll
                for (int j = 0; j < 8; ++j)
                    acc[i][j] = fmaf(a[i], b[j], acc[i][j]);
        }
    }
#pragma unroll
    for (int i = 0; i < 8; ++i) {
        int row = m0 + ((i < 4) ? (tm + i) : (64 + tm + i - 4));
        float* Cr = g_t + row * HID + n0;
        *(float4*)(Cr + tn)      = make_float4(acc[i][0], acc[i][1], acc[i][2], acc[i][3]);
        *(float4*)(Cr + 64 + tn) = make_float4(acc[i][4], acc[i][5], acc[i][6], acc[i][7]);
    }
}

// ---------------- aggregation (warp per dst, CSR) + bias + relu -> g_h ----------------
__global__ void agg_kernel(const float* __restrict__ bias)
{
    int lane = threadIdx.x & 31;
    int node = (blockIdx.x * blockDim.x + threadIdx.x) >> 5;
    if (node >= N_NODES) return;
    int e = g_rowptr[node], e_end = g_rowptr[node + 1];
    float4 acc0 = make_float4(0, 0, 0, 0);
    float4 acc1 = make_float4(0, 0, 0, 0);
    const float4* T = (const float4*)g_t;
    for (; e < e_end; ++e) {
        int2 sw = g_csr[e];
        float w = __int_as_float(sw.y);
        int base = sw.x * (HID / 4);
        float4 a = __ldg(T + base + lane);
        float4 b = __ldg(T + base + 32 + lane);
        acc0.x = fmaf(w, a.x, acc0.x); acc0.y = fmaf(w, a.y, acc0.y);
        acc0.z = fmaf(w, a.z, acc0.z); acc0.w = fmaf(w, a.w, acc0.w);
        acc1.x = fmaf(w, b.x, acc1.x); acc1.y = fmaf(w, b.y, acc1.y);
        acc1.z = fmaf(w, b.z, acc1.z); acc1.w = fmaf(w, b.w, acc1.w);
    }
    float di = g_dinv[node];
    int base = node * (HID / 4);
    {   // self loop
        float4 a = __ldg(T + base + lane);
        float4 b = __ldg(T + base + 32 + lane);
        acc0.x = fmaf(di, a.x, acc0.x); acc0.y = fmaf(di, a.y, acc0.y);
        acc0.z = fmaf(di, a.z, acc0.z); acc0.w = fmaf(di, a.w, acc0.w);
        acc1.x = fmaf(di, b.x, acc1.x); acc1.y = fmaf(di, b.y, acc1.y);
        acc1.z = fmaf(di, b.z, acc1.z); acc1.w = fmaf(di, b.w, acc1.w);
    }
    float4 bb0 = *(const float4*)(bias + lane * 4);
    float4 bb1 = *(const float4*)(bias + 128 + lane * 4);
    float4 o0, o1;
    o0.x = fmaxf(fmaf(acc0.x, di, bb0.x), 0.0f);
    o0.y = fmaxf(fmaf(acc0.y, di, bb0.y), 0.0f);
    o0.z = fmaxf(fmaf(acc0.z, di, bb0.z), 0.0f);
    o0.w = fmaxf(fmaf(acc0.w, di, bb0.w), 0.0f);
    o1.x = fmaxf(fmaf(acc1.x, di, bb1.x), 0.0f);
    o1.y = fmaxf(fmaf(acc1.y, di, bb1.y), 0.0f);
    o1.z = fmaxf(fmaf(acc1.z, di, bb1.z), 0.0f);
    o1.w = fmaxf(fmaf(acc1.w, di, bb1.w), 0.0f);
    float4* H = (float4*)g_h;
    H[base + lane] = o0;
    H[base + 32 + lane] = o1;
}

__global__ void dropout_kernel(uint32_t k0, uint32_t k1)
{
    int e = blockIdx.x * blockDim.x + threadIdx.x;
    if (e >= NH) return;
    g_h[e] = apply_dropout(g_h[e], k0, k1, (uint32_t)e);
}

// ---------------- per-node heads: out[i,p] = h[i,:] @ Wq[i,:,p] + bq[i,p] ----------------
__global__ void head_kernel(const float* __restrict__ Wq,
                            const float* __restrict__ bq,
                            float* __restrict__ out)
{
    int lane = threadIdx.x & 31;
    int node = (blockIdx.x * blockDim.x + threadIdx.x) >> 5;
    if (node >= N_NODES) return;
    const float* hrow = g_h + node * HID;
    const float4* wrow = (const float4*)(Wq + (size_t)node * (HID * 8));
    float acc[8] = {0, 0, 0, 0, 0, 0, 0, 0};
#pragma unroll
    for (int u = 0; u < 8; ++u) {
        int hidx = u * 32 + lane;
        float s = hrow[hidx];
        float4 w0 = __ldg(wrow + hidx * 2);
        float4 w1 = __ldg(wrow + hidx * 2 + 1);
        acc[0] = fmaf(s, w0.x, acc[0]); acc[1] = fmaf(s, w0.y, acc[1]);
        acc[2] = fmaf(s, w0.z, acc[2]); acc[3] = fmaf(s, w0.w, acc[3]);
        acc[4] = fmaf(s, w1.x, acc[4]); acc[5] = fmaf(s, w1.y, acc[5]);
        acc[6] = fmaf(s, w1.z, acc[6]); acc[7] = fmaf(s, w1.w, acc[7]);
    }
#pragma unroll
    for (int d = 16; d; d >>= 1)
#pragma unroll
        for (int i = 0; i < 8; ++i)
            acc[i] += __shfl_xor_sync(0xffffffffu, acc[i], d);
    if (lane == 0) {
#pragma unroll
        for (int i = 0; i < 8; ++i)
            out[node * 8 + i] = acc[i] + bq[node * 8 + i];
    }
}

// ---------------- launch ----------------
extern "C" void kernel_launch(void* const* d_in, const int* in_sizes, int n_in,
                              void* d_out, int out_size)
{
    const float* x  = (const float*)d_in[0];
    const void*  ei = d_in[1];
    const float* W0 = (const float*)d_in[2];
    const float* b0 = (const float*)d_in[3];
    const float* W1 = (const float*)d_in[4];
    const float* b1 = (const float*)d_in[5];
    const float* W2 = (const float*)d_in[6];
    const float* b2 = (const float*)d_in[7];
    const float* Wq = (const float*)d_in[8];
    const float* bq = (const float*)d_in[9];
    float* out = (float*)d_out;

    // JAX: dk = split(key(42), 3); partitionable (foldlike) split:
    //   dk[i] = threefry((0,42), hi=0, lo=i) -> (o0, o1)
    uint32_t dk[3][2];
    for (uint32_t i = 0; i < 3; ++i)
        threefry2x32(0u, 42u, 0u, i, &dk[i][0], &dk[i][1]);

    detect_kernel<<<1, 1>>>((const unsigned int*)ei);
    init_kernel<<<(N_NODES + 255) / 256, 256>>>();
    convert_kernel<<<(E_EDGES + 255) / 256, 256>>>(ei);
    scan_kernel<<<1, 1024>>>();
    scatter_kernel<<<(E_EDGES + 255) / 256, 256>>>();

    aggx_kernel<<<(N_NODES * 32 + 255) / 256, 256>>>(x);
    expand_l1_kernel<<<NH / 256, 256>>>(W0, b0, dk[0][0], dk[0][1]);

    gemm_kernel<<<dim3(NPAD / 128, 2), 256>>>(W1);
    agg_kernel<<<(N_NODES * 32 + 255) / 256, 256>>>(b1);
    dropout_kernel<<<NH / 256, 256>>>(dk[1][0], dk[1][1]);

    gemm_kernel<<<dim3(NPAD / 128, 2), 256>>>(W2);
    agg_kernel<<<(N_NODES * 32 + 255) / 256, 256>>>(b2);
    dropout_kernel<<<NH / 256, 256>>>(dk[2][0], dk[2][1]);

    head_kernel<<<(N_NODES * 32 + 255) / 256, 256>>>(Wq, bq, out);
}

// round 3
// speedup vs baseline: 1.0841x; 1.0841x over previous
#include <cuda_runtime.h>
#include <stdint.h>

#define N_NODES 20000
#define NPAD    20096           // 157 * 128
#define HID     256
#define E_EDGES 640000
#define NH      (N_NODES * HID) // 5,120,000

// ---------------- scratch (device globals; no allocation) ----------------
__device__ int   g_is64;
__device__ int   g_deg[N_NODES];
__device__ int   g_cursor[N_NODES];
__device__ int   g_rowptr[N_NODES + 1];
__device__ int   g_srcA[E_EDGES];
__device__ int   g_dstA[E_EDGES];
__device__ int2  g_csr[E_EDGES];        // (src, bitcast(dinv[src]))
__device__ float g_dinv[N_NODES];
__device__ float g_aggx[N_NODES];
__device__ float g_h[NPAD * HID];       // padded rows stay zero forever
__device__ float g_t[NPAD * HID];

// ---------------- threefry2x32 (JAX-exact) ----------------
__host__ __device__ __forceinline__ void threefry2x32(
    uint32_t k0, uint32_t k1, uint32_t x0, uint32_t x1,
    uint32_t* o0, uint32_t* o1)
{
    uint32_t ks2 = k0 ^ k1 ^ 0x1BD11BDAu;
    x0 += k0; x1 += k1;
#define TF_R(r) { x0 += x1; x1 = (x1 << (r)) | (x1 >> (32 - (r))); x1 ^= x0; }
    TF_R(13) TF_R(15) TF_R(26) TF_R(6)
    x0 += k1; x1 += ks2 + 1u;
    TF_R(17) TF_R(29) TF_R(16) TF_R(24)
    x0 += ks2; x1 += k0 + 2u;
    TF_R(13) TF_R(15) TF_R(26) TF_R(6)
    x0 += k0; x1 += k1 + 3u;
    TF_R(17) TF_R(29) TF_R(16) TF_R(24)
    x0 += k1; x1 += ks2 + 4u;
    TF_R(13) TF_R(15) TF_R(26) TF_R(6)
    x0 += ks2; x1 += k0 + 5u;
#undef TF_R
    *o0 = x0; *o1 = x1;
}

// JAX partitionable threefry: bits32[e] = o0 ^ o1 at counter (0, e);
// keep <=> bit31 == 0; kept values scaled by 1/(1-p) = 2.
__device__ __forceinline__ float apply_dropout(float v, uint32_t k0, uint32_t k1, uint32_t e)
{
    uint32_t o0, o1;
    threefry2x32(k0, k1, 0u, e, &o0, &o1);
    return ((o0 ^ o1) & 0x80000000u) ? 0.0f : 2.0f * v;
}

// ---------------- preprocessing ----------------
__global__ void detect_kernel(const unsigned int* __restrict__ w)
{
    int z = 1;
    for (int k = 0; k < 64; ++k)
        if (w[2 * k + 1] != 0u) { z = 0; break; }
    g_is64 = z;
}

__global__ void init_kernel()
{
    int i = blockIdx.x * blockDim.x + threadIdx.x;
    if (i < N_NODES) { g_deg[i] = 0; g_cursor[i] = 0; }
}

__global__ void convert_kernel(const void* __restrict__ ei)
{
    int e = blockIdx.x * blockDim.x + threadIdx.x;
    if (e >= E_EDGES) return;
    int s, d;
    if (g_is64) {
        const long long* p = (const long long*)ei;
        s = (int)p[e]; d = (int)p[E_EDGES + e];
    } else {
        const int* p = (const int*)ei;
        s = p[e]; d = p[E_EDGES + e];
    }
    g_srcA[e] = s; g_dstA[e] = d;
    atomicAdd(&g_deg[d], 1);
}

// single block, 1024 threads, 20 elems/thread; two-level shuffle scan
__global__ void scan_kernel()
{
    const int CH = 20;  // 1024*20 = 20480 >= 20000
    __shared__ int warp_sums[32];
    int t = threadIdx.x;
    int base = t * CH;
    int local[CH];
    int sum = 0;
#pragma unroll
    for (int j = 0; j < CH; ++j) {
        int i = base + j;
        int v = (i < N_NODES) ? g_deg[i] : 0;
        local[j] = sum;               // thread-local exclusive prefix
        sum += v;
        if (i < N_NODES) g_dinv[i] = rsqrtf((float)(v + 1));  // +1 self loop
    }
    int lane = t & 31, wid = t >> 5;
    int s = sum;
#pragma unroll
    for (int d = 1; d < 32; d <<= 1) {
        int n = __shfl_up_sync(0xffffffffu, s, d);
        if (lane >= d) s += n;
    }
    if (lane == 31) warp_sums[wid] = s;   // inclusive warp total
    __syncthreads();
    if (wid == 0) {
        int w = warp_sums[lane];
#pragma unroll
        for (int d = 1; d < 32; d <<= 1) {
            int n = __shfl_up_sync(0xffffffffu, w, d);
            if (lane >= d) w += n;
        }
        warp_sums[lane] = w;              // inclusive scan of warp totals
    }
    __syncthreads();
    int offset = (s - sum) + (wid ? warp_sums[wid - 1] : 0);
#pragma unroll
    for (int j = 0; j < CH; ++j) {
        int i = base + j;
        if (i < N_NODES) g_rowptr[i] = offset + local[j];
    }
    if (t == 1023) g_rowptr[N_NODES] = warp_sums[31];
}

__global__ void scatter_kernel()
{
    int e = blockIdx.x * blockDim.x + threadIdx.x;
    if (e >= E_EDGES) return;
    int d = g_dstA[e], s = g_srcA[e];
    int pos = g_rowptr[d] + atomicAdd(&g_cursor[d], 1);
    g_csr[pos] = make_int2(s, __float_as_int(g_dinv[s]));
}

// ---------------- layer 1 (Fin = 1 rewrite) ----------------
__global__ void aggx_kernel(const float* __restrict__ x)
{
    int lane = threadIdx.x & 31;
    int node = (blockIdx.x * blockDim.x + threadIdx.x) >> 5;
    if (node >= N_NODES) return;
    int s = g_rowptr[node], e_end = g_rowptr[node + 1];
    float sum = 0.0f;
    for (int e = s + lane; e < e_end; e += 32) {
        int2 sw = g_csr[e];
        sum = fmaf(__int_as_float(sw.y), __ldg(x + sw.x), sum);
    }
#pragma unroll
    for (int d = 16; d; d >>= 1) sum += __shfl_xor_sync(0xffffffffu, sum, d);
    if (lane == 0) {
        float di = g_dinv[node];
        g_aggx[node] = di * fmaf(di, __ldg(x + node), sum);
    }
}

__global__ void expand_l1_kernel(const float* __restrict__ W0,
                                 const float* __restrict__ b0,
                                 uint32_t k0, uint32_t k1)
{
    int e = blockIdx.x * blockDim.x + threadIdx.x;
    if (e >= NH) return;
    int i = e >> 8, j = e & 255;
    float v = fmaxf(fmaf(g_aggx[i], W0[j], b0[j]), 0.0f);
    g_h[e] = apply_dropout(v, k0, k1, (uint32_t)e);
}

// ---------------- GEMM: g_t = g_h @ B   (NPAD x 256) x (256 x 256) ----------------
__global__ void gemm_kernel(const float* __restrict__ B)
{
    __shared__ float As[8][132];
    __shared__ float Bs[8][132];
    int tid = threadIdx.x;
    int m0 = blockIdx.x * 128;
    int n0 = blockIdx.y * 128;
    int tm = (tid >> 4) * 4;
    int tn = (tid & 15) * 4;

    float acc[8][8];
#pragma unroll
    for (int i = 0; i < 8; ++i)
#pragma unroll
        for (int j = 0; j < 8; ++j) acc[i][j] = 0.0f;

    int arow = tid >> 1;
    int aseg = (tid & 1) * 4;
    int brow = tid >> 5;
    int bseg = (tid & 31) * 4;
    const float* Ag = g_h + (m0 + arow) * HID + aseg;
    const float* Bg = B + brow * HID + n0 + bseg;

    for (int kt = 0; kt < 256; kt += 8) {
        float4 av = *(const float4*)(Ag + kt);
        float4 bv = *(const float4*)(Bg + kt * HID);
        __syncthreads();
        As[aseg + 0][arow] = av.x;
        As[aseg + 1][arow] = av.y;
        As[aseg + 2][arow] = av.z;
        As[aseg + 3][arow] = av.w;
        *(float4*)&Bs[brow][bseg] = bv;
        __syncthreads();
#pragma unroll
        for (int k = 0; k < 8; ++k) {
            float a[8], b[8];
            *(float4*)(a)     = *(const float4*)&As[k][tm];
            *(float4*)(a + 4) = *(const float4*)&As[k][64 + tm];
            *(float4*)(b)     = *(const float4*)&Bs[k][tn];
            *(float4*)(b + 4) = *(const float4*)&Bs[k][64 + tn];
#pragma unroll
            for (int i = 0; i < 8; ++i)
#pragma unroll
                for (int j = 0; j < 8; ++j)
                    acc[i][j] = fmaf(a[i], b[j], acc[i][j]);
        }
    }
#pragma unroll
    for (int i = 0; i < 8; ++i) {
        int row = m0 + ((i < 4) ? (tm + i) : (64 + tm + i - 4));
        float* Cr = g_t + row * HID + n0;
        *(float4*)(Cr + tn)      = make_float4(acc[i][0], acc[i][1], acc[i][2], acc[i][3]);
        *(float4*)(Cr + 64 + tn) = make_float4(acc[i][4], acc[i][5], acc[i][6], acc[i][7]);
    }
}

// ---------------- aggregation + bias + relu + dropout (fused) -> g_h ----------------
__global__ void agg_kernel(const float* __restrict__ bias, uint32_t k0, uint32_t k1)
{
    int lane = threadIdx.x & 31;
    int node = (blockIdx.x * blockDim.x + threadIdx.x) >> 5;
    if (node >= N_NODES) return;
    int e = g_rowptr[node], e_end = g_rowptr[node + 1];
    float4 acc0 = make_float4(0, 0, 0, 0);
    float4 acc1 = make_float4(0, 0, 0, 0);
    const float4* T = (const float4*)g_t;
    for (; e < e_end; ++e) {
        int2 sw = g_csr[e];
        float w = __int_as_float(sw.y);
        int base = sw.x * (HID / 4);
        float4 a = __ldg(T + base + lane);
        float4 b = __ldg(T + base + 32 + lane);
        acc0.x = fmaf(w, a.x, acc0.x); acc0.y = fmaf(w, a.y, acc0.y);
        acc0.z = fmaf(w, a.z, acc0.z); acc0.w = fmaf(w, a.w, acc0.w);
        acc1.x = fmaf(w, b.x, acc1.x); acc1.y = fmaf(w, b.y, acc1.y);
        acc1.z = fmaf(w, b.z, acc1.z); acc1.w = fmaf(w, b.w, acc1.w);
    }
    float di = g_dinv[node];
    int base = node * (HID / 4);
    {   // self loop
        float4 a = __ldg(T + base + lane);
        float4 b = __ldg(T + base + 32 + lane);
        acc0.x = fmaf(di, a.x, acc0.x); acc0.y = fmaf(di, a.y, acc0.y);
        acc0.z = fmaf(di, a.z, acc0.z); acc0.w = fmaf(di, a.w, acc0.w);
        acc1.x = fmaf(di, b.x, acc1.x); acc1.y = fmaf(di, b.y, acc1.y);
        acc1.z = fmaf(di, b.z, acc1.z); acc1.w = fmaf(di, b.w, acc1.w);
    }
    float4 bb0 = *(const float4*)(bias + lane * 4);
    float4 bb1 = *(const float4*)(bias + 128 + lane * 4);
    float4 o0, o1;
    o0.x = fmaxf(fmaf(acc0.x, di, bb0.x), 0.0f);
    o0.y = fmaxf(fmaf(acc0.y, di, bb0.y), 0.0f);
    o0.z = fmaxf(fmaf(acc0.z, di, bb0.z), 0.0f);
    o0.w = fmaxf(fmaf(acc0.w, di, bb0.w), 0.0f);
    o1.x = fmaxf(fmaf(acc1.x, di, bb1.x), 0.0f);
    o1.y = fmaxf(fmaf(acc1.y, di, bb1.y), 0.0f);
    o1.z = fmaxf(fmaf(acc1.z, di, bb1.z), 0.0f);
    o1.w = fmaxf(fmaf(acc1.w, di, bb1.w), 0.0f);
    // fused dropout (element index = node*256 + channel)
    uint32_t e0 = (uint32_t)(node * HID + lane * 4);
    uint32_t e1 = e0 + 128;
    o0.x = apply_dropout(o0.x, k0, k1, e0 + 0);
    o0.y = apply_dropout(o0.y, k0, k1, e0 + 1);
    o0.z = apply_dropout(o0.z, k0, k1, e0 + 2);
    o0.w = apply_dropout(o0.w, k0, k1, e0 + 3);
    o1.x = apply_dropout(o1.x, k0, k1, e1 + 0);
    o1.y = apply_dropout(o1.y, k0, k1, e1 + 1);
    o1.z = apply_dropout(o1.z, k0, k1, e1 + 2);
    o1.w = apply_dropout(o1.w, k0, k1, e1 + 3);
    float4* H = (float4*)g_h;
    H[base + lane] = o0;
    H[base + 32 + lane] = o1;
}

// ---------------- per-node heads ----------------
__global__ void head_kernel(const float* __restrict__ Wq,
                            const float* __restrict__ bq,
                            float* __restrict__ out)
{
    int lane = threadIdx.x & 31;
    int node = (blockIdx.x * blockDim.x + threadIdx.x) >> 5;
    if (node >= N_NODES) return;
    const float* hrow = g_h + node * HID;
    const float4* wrow = (const float4*)(Wq + (size_t)node * (HID * 8));
    float acc[8] = {0, 0, 0, 0, 0, 0, 0, 0};
#pragma unroll
    for (int u = 0; u < 8; ++u) {
        int hidx = u * 32 + lane;
        float s = hrow[hidx];
        float4 w0 = __ldg(wrow + hidx * 2);
        float4 w1 = __ldg(wrow + hidx * 2 + 1);
        acc[0] = fmaf(s, w0.x, acc[0]); acc[1] = fmaf(s, w0.y, acc[1]);
        acc[2] = fmaf(s, w0.z, acc[2]); acc[3] = fmaf(s, w0.w, acc[3]);
        acc[4] = fmaf(s, w1.x, acc[4]); acc[5] = fmaf(s, w1.y, acc[5]);
        acc[6] = fmaf(s, w1.z, acc[6]); acc[7] = fmaf(s, w1.w, acc[7]);
    }
#pragma unroll
    for (int d = 16; d; d >>= 1)
#pragma unroll
        for (int i = 0; i < 8; ++i)
            acc[i] += __shfl_xor_sync(0xffffffffu, acc[i], d);
    if (lane == 0) {
#pragma unroll
        for (int i = 0; i < 8; ++i)
            out[node * 8 + i] = acc[i] + bq[node * 8 + i];
    }
}

// ---------------- launch ----------------
extern "C" void kernel_launch(void* const* d_in, const int* in_sizes, int n_in,
                              void* d_out, int out_size)
{
    const float* x  = (const float*)d_in[0];
    const void*  ei = d_in[1];
    const float* W0 = (const float*)d_in[2];
    const float* b0 = (const float*)d_in[3];
    const float* W1 = (const float*)d_in[4];
    const float* b1 = (const float*)d_in[5];
    const float* W2 = (const float*)d_in[6];
    const float* b2 = (const float*)d_in[7];
    const float* Wq = (const float*)d_in[8];
    const float* bq = (const float*)d_in[9];
    float* out = (float*)d_out;

    uint32_t dk[3][2];
    for (uint32_t i = 0; i < 3; ++i)
        threefry2x32(0u, 42u, 0u, i, &dk[i][0], &dk[i][1]);

    detect_kernel<<<1, 1>>>((const unsigned int*)ei);
    init_kernel<<<(N_NODES + 255) / 256, 256>>>();
    convert_kernel<<<(E_EDGES + 255) / 256, 256>>>(ei);
    scan_kernel<<<1, 1024>>>();
    scatter_kernel<<<(E_EDGES + 255) / 256, 256>>>();

    aggx_kernel<<<(N_NODES * 32 + 255) / 256, 256>>>(x);
    expand_l1_kernel<<<NH / 256, 256>>>(W0, b0, dk[0][0], dk[0][1]);

    gemm_kernel<<<dim3(NPAD / 128, 2), 256>>>(W1);
    agg_kernel<<<(N_NODES * 32 + 255) / 256, 256>>>(b1, dk[1][0], dk[1][1]);

    gemm_kernel<<<dim3(NPAD / 128, 2), 256>>>(W2);
    agg_kernel<<<(N_NODES * 32 + 255) / 256, 256>>>(b2, dk[2][0], dk[2][1]);

    head_kernel<<<(N_NODES * 32 + 255) / 256, 256>>>(Wq, bq, out);
}

// round 4
// speedup vs baseline: 1.1538x; 1.0643x over previous
#include <cuda_runtime.h>
#include <stdint.h>

#define N_NODES 20000
#define NPAD    20096           // 157 * 128
#define HID     256
#define E_EDGES 640000
#define NH      (N_NODES * HID) // 5,120,000

// ---------------- scratch (device globals; no allocation) ----------------
__device__ int   g_is64;
__device__ int   g_deg[N_NODES];
__device__ int   g_cursor[N_NODES];
__device__ int   g_rowptr[N_NODES + 1];
__device__ int   g_srcA[E_EDGES];
__device__ int   g_dstA[E_EDGES];
__device__ int2  g_csr[E_EDGES];        // (src, bitcast(dinv[src]))
__device__ float g_dinv[N_NODES];
__device__ float g_aggx[N_NODES];
__device__ float g_h[NPAD * HID];       // padded rows stay zero forever
__device__ float g_t[NPAD * HID];

// ---------------- packed f32x2 helpers (sm_103a FFMA2 path) ----------------
__device__ __forceinline__ uint64_t pack2_dup(float x)
{
    uint64_t r;
    asm("mov.b64 %0, {%1, %1};" : "=l"(r) : "f"(x));
    return r;
}
__device__ __forceinline__ void fma2(uint64_t& d, uint64_t a, uint64_t b)
{
    asm("fma.rn.f32x2 %0, %1, %2, %0;" : "+l"(d) : "l"(a), "l"(b));
}
__device__ __forceinline__ float2 unpack2(uint64_t v)
{
    float2 r;
    asm("mov.b64 {%0, %1}, %2;" : "=f"(r.x), "=f"(r.y) : "l"(v));
    return r;
}

// ---------------- threefry2x32 (JAX-exact) ----------------
__host__ __device__ __forceinline__ void threefry2x32(
    uint32_t k0, uint32_t k1, uint32_t x0, uint32_t x1,
    uint32_t* o0, uint32_t* o1)
{
    uint32_t ks2 = k0 ^ k1 ^ 0x1BD11BDAu;
    x0 += k0; x1 += k1;
#define TF_R(r) { x0 += x1; x1 = (x1 << (r)) | (x1 >> (32 - (r))); x1 ^= x0; }
    TF_R(13) TF_R(15) TF_R(26) TF_R(6)
    x0 += k1; x1 += ks2 + 1u;
    TF_R(17) TF_R(29) TF_R(16) TF_R(24)
    x0 += ks2; x1 += k0 + 2u;
    TF_R(13) TF_R(15) TF_R(26) TF_R(6)
    x0 += k0; x1 += k1 + 3u;
    TF_R(17) TF_R(29) TF_R(16) TF_R(24)
    x0 += k1; x1 += ks2 + 4u;
    TF_R(13) TF_R(15) TF_R(26) TF_R(6)
    x0 += ks2; x1 += k0 + 5u;
#undef TF_R
    *o0 = x0; *o1 = x1;
}

// JAX partitionable threefry: bits32[e] = o0 ^ o1 at counter (0, e);
// keep <=> bit31 == 0; kept values scaled by 1/(1-p) = 2.
__device__ __forceinline__ float apply_dropout(float v, uint32_t k0, uint32_t k1, uint32_t e)
{
    uint32_t o0, o1;
    threefry2x32(k0, k1, 0u, e, &o0, &o1);
    return ((o0 ^ o1) & 0x80000000u) ? 0.0f : 2.0f * v;
}

// ---------------- preprocessing ----------------
__global__ void detect_kernel(const unsigned int* __restrict__ w)
{
    int lane = threadIdx.x;
    int z = (w[4 * lane + 1] == 0u) && (w[4 * lane + 3] == 0u);
    unsigned m = __ballot_sync(0xffffffffu, z);
    if (lane == 0) g_is64 = (m == 0xffffffffu);
}

__global__ void init_kernel()
{
    int i = blockIdx.x * blockDim.x + threadIdx.x;
    if (i < N_NODES) { g_deg[i] = 0; g_cursor[i] = 0; }
}

__global__ void convert_kernel(const void* __restrict__ ei)
{
    int e = blockIdx.x * blockDim.x + threadIdx.x;
    if (e >= E_EDGES) return;
    int s, d;
    if (g_is64) {
        const long long* p = (const long long*)ei;
        s = (int)p[e]; d = (int)p[E_EDGES + e];
    } else {
        const int* p = (const int*)ei;
        s = p[e]; d = p[E_EDGES + e];
    }
    g_srcA[e] = s; g_dstA[e] = d;
    atomicAdd(&g_deg[d], 1);
}

// single block, 1024 threads, 20 elems/thread, TWO passes (no per-thread array)
__global__ void scan_kernel()
{
    const int CH = 20;  // 1024*20 = 20480 >= 20000
    __shared__ int warp_sums[32];
    int t = threadIdx.x;
    int base = t * CH;
    int lim = (base + CH <= N_NODES) ? CH : (base < N_NODES ? N_NODES - base : 0);

    int sum = 0;
#pragma unroll 4
    for (int j = 0; j < lim; ++j) {
        int v = g_deg[base + j];
        sum += v;
        g_dinv[base + j] = rsqrtf((float)(v + 1));  // +1 self loop
    }
    int lane = t & 31, wid = t >> 5;
    int s = sum;
#pragma unroll
    for (int d = 1; d < 32; d <<= 1) {
        int n = __shfl_up_sync(0xffffffffu, s, d);
        if (lane >= d) s += n;
    }
    if (lane == 31) warp_sums[wid] = s;
    __syncthreads();
    if (wid == 0) {
        int w = warp_sums[lane];
#pragma unroll
        for (int d = 1; d < 32; d <<= 1) {
            int n = __shfl_up_sync(0xffffffffu, w, d);
            if (lane >= d) w += n;
        }
        warp_sums[lane] = w;
    }
    __syncthreads();
    int run = (s - sum) + (wid ? warp_sums[wid - 1] : 0);
#pragma unroll 4
    for (int j = 0; j < lim; ++j) {
        g_rowptr[base + j] = run;
        run += g_deg[base + j];
    }
    if (t == 1023) g_rowptr[N_NODES] = warp_sums[31];
}

__global__ void scatter_kernel()
{
    int e = blockIdx.x * blockDim.x + threadIdx.x;
    if (e >= E_EDGES) return;
    int d = g_dstA[e], s = g_srcA[e];
    int pos = g_rowptr[d] + atomicAdd(&g_cursor[d], 1);
    g_csr[pos] = make_int2(s, __float_as_int(g_dinv[s]));
}

// ---------------- layer 1 (Fin = 1 rewrite) ----------------
__global__ void aggx_kernel(const float* __restrict__ x)
{
    int lane = threadIdx.x & 31;
    int node = (blockIdx.x * blockDim.x + threadIdx.x) >> 5;
    if (node >= N_NODES) return;
    int s = g_rowptr[node], e_end = g_rowptr[node + 1];
    float sum = 0.0f;
    for (int e = s + lane; e < e_end; e += 32) {
        int2 sw = g_csr[e];
        sum = fmaf(__int_as_float(sw.y), __ldg(x + sw.x), sum);
    }
#pragma unroll
    for (int d = 16; d; d >>= 1) sum += __shfl_xor_sync(0xffffffffu, sum, d);
    if (lane == 0) {
        float di = g_dinv[node];
        g_aggx[node] = di * fmaf(di, __ldg(x + node), sum);
    }
}

__global__ void expand_l1_kernel(const float* __restrict__ W0,
                                 const float* __restrict__ b0,
                                 uint32_t k0, uint32_t k1)
{
    int e = blockIdx.x * blockDim.x + threadIdx.x;
    if (e >= NH) return;
    int i = e >> 8, j = e & 255;
    float v = fmaxf(fmaf(g_aggx[i], W0[j], b0[j]), 0.0f);
    g_h[e] = apply_dropout(v, k0, k1, (uint32_t)e);
}

// ---------------- GEMM: g_t = g_h @ B, packed f32x2 accumulation ----------------
__global__ void __launch_bounds__(256, 2) gemm_kernel(const float* __restrict__ B)
{
    __shared__ float As[8][132];
    __shared__ float Bs[8][132];
    int tid = threadIdx.x;
    int m0 = blockIdx.x * 128;
    int n0 = blockIdx.y * 128;
    int tm = (tid >> 4) * 4;   // rows {tm..tm+3} and {64+tm..}
    int tn = (tid & 15) * 4;   // cols {tn..tn+3} and {64+tn..}

    // acc[i][p]: i = 8 rows, p = 4 packed col-pairs (j0j1, j2j3, j4j5, j6j7)
    uint64_t acc[8][4];
#pragma unroll
    for (int i = 0; i < 8; ++i)
#pragma unroll
        for (int p = 0; p < 4; ++p) acc[i][p] = 0ull;

    int arow = tid >> 1;
    int aseg = (tid & 1) * 4;
    int brow = tid >> 5;
    int bseg = (tid & 31) * 4;
    const float* Ag = g_h + (m0 + arow) * HID + aseg;
    const float* Bg = B + brow * HID + n0 + bseg;

    for (int kt = 0; kt < 256; kt += 8) {
        float4 av = *(const float4*)(Ag + kt);
        float4 bv = *(const float4*)(Bg + kt * HID);
        __syncthreads();
        As[aseg + 0][arow] = av.x;
        As[aseg + 1][arow] = av.y;
        As[aseg + 2][arow] = av.z;
        As[aseg + 3][arow] = av.w;
        *(float4*)&Bs[brow][bseg] = bv;
        __syncthreads();
#pragma unroll
        for (int k = 0; k < 8; ++k) {
            float a[8];
            *(float4*)(a)     = *(const float4*)&As[k][tm];
            *(float4*)(a + 4) = *(const float4*)&As[k][64 + tm];
            uint64_t bp[4];
            bp[0] = *(const uint64_t*)&Bs[k][tn];
            bp[1] = *(const uint64_t*)&Bs[k][tn + 2];
            bp[2] = *(const uint64_t*)&Bs[k][64 + tn];
            bp[3] = *(const uint64_t*)&Bs[k][64 + tn + 2];
#pragma unroll
            for (int i = 0; i < 8; ++i) {
                uint64_t aa = pack2_dup(a[i]);
                fma2(acc[i][0], aa, bp[0]);
                fma2(acc[i][1], aa, bp[1]);
                fma2(acc[i][2], aa, bp[2]);
                fma2(acc[i][3], aa, bp[3]);
            }
        }
    }
#pragma unroll
    for (int i = 0; i < 8; ++i) {
        int row = m0 + ((i < 4) ? (tm + i) : (64 + tm + i - 4));
        float* Cr = g_t + row * HID + n0;
        float2 p0 = unpack2(acc[i][0]);
        float2 p1 = unpack2(acc[i][1]);
        float2 p2 = unpack2(acc[i][2]);
        float2 p3 = unpack2(acc[i][3]);
        *(float4*)(Cr + tn)      = make_float4(p0.x, p0.y, p1.x, p1.y);
        *(float4*)(Cr + 64 + tn) = make_float4(p2.x, p2.y, p3.x, p3.y);
    }
}

// ---------------- aggregation + bias + relu + dropout (fused) -> g_h ----------------
__global__ void agg_kernel(const float* __restrict__ bias, uint32_t k0, uint32_t k1)
{
    int lane = threadIdx.x & 31;
    int node = (blockIdx.x * blockDim.x + threadIdx.x) >> 5;
    if (node >= N_NODES) return;
    int e = g_rowptr[node], e_end = g_rowptr[node + 1];
    float4 acc0 = make_float4(0, 0, 0, 0);
    float4 acc1 = make_float4(0, 0, 0, 0);
    const float4* T = (const float4*)g_t;
    for (; e < e_end; ++e) {
        int2 sw = g_csr[e];
        float w = __int_as_float(sw.y);
        int base = sw.x * (HID / 4);
        float4 a = __ldg(T + base + lane);
        float4 b = __ldg(T + base + 32 + lane);
        acc0.x = fmaf(w, a.x, acc0.x); acc0.y = fmaf(w, a.y, acc0.y);
        acc0.z = fmaf(w, a.z, acc0.z); acc0.w = fmaf(w, a.w, acc0.w);
        acc1.x = fmaf(w, b.x, acc1.x); acc1.y = fmaf(w, b.y, acc1.y);
        acc1.z = fmaf(w, b.z, acc1.z); acc1.w = fmaf(w, b.w, acc1.w);
    }
    float di = g_dinv[node];
    int base = node * (HID / 4);
    {   // self loop
        float4 a = __ldg(T + base + lane);
        float4 b = __ldg(T + base + 32 + lane);
        acc0.x = fmaf(di, a.x, acc0.x); acc0.y = fmaf(di, a.y, acc0.y);
        acc0.z = fmaf(di, a.z, acc0.z); acc0.w = fmaf(di, a.w, acc0.w);
        acc1.x = fmaf(di, b.x, acc1.x); acc1.y = fmaf(di, b.y, acc1.y);
        acc1.z = fmaf(di, b.z, acc1.z); acc1.w = fmaf(di, b.w, acc1.w);
    }
    float4 bb0 = *(const float4*)(bias + lane * 4);
    float4 bb1 = *(const float4*)(bias + 128 + lane * 4);
    float4 o0, o1;
    o0.x = fmaxf(fmaf(acc0.x, di, bb0.x), 0.0f);
    o0.y = fmaxf(fmaf(acc0.y, di, bb0.y), 0.0f);
    o0.z = fmaxf(fmaf(acc0.z, di, bb0.z), 0.0f);
    o0.w = fmaxf(fmaf(acc0.w, di, bb0.w), 0.0f);
    o1.x = fmaxf(fmaf(acc1.x, di, bb1.x), 0.0f);
    o1.y = fmaxf(fmaf(acc1.y, di, bb1.y), 0.0f);
    o1.z = fmaxf(fmaf(acc1.z, di, bb1.z), 0.0f);
    o1.w = fmaxf(fmaf(acc1.w, di, bb1.w), 0.0f);
    uint32_t e0 = (uint32_t)(node * HID + lane * 4);
    uint32_t e1 = e0 + 128;
    o0.x = apply_dropout(o0.x, k0, k1, e0 + 0);
    o0.y = apply_dropout(o0.y, k0, k1, e0 + 1);
    o0.z = apply_dropout(o0.z, k0, k1, e0 + 2);
    o0.w = apply_dropout(o0.w, k0, k1, e0 + 3);
    o1.x = apply_dropout(o1.x, k0, k1, e1 + 0);
    o1.y = apply_dropout(o1.y, k0, k1, e1 + 1);
    o1.z = apply_dropout(o1.z, k0, k1, e1 + 2);
    o1.w = apply_dropout(o1.w, k0, k1, e1 + 3);
    float4* H = (float4*)g_h;
    H[base + lane] = o0;
    H[base + 32 + lane] = o1;
}

// ---------------- per-node heads ----------------
__global__ void head_kernel(const float* __restrict__ Wq,
                            const float* __restrict__ bq,
                            float* __restrict__ out)
{
    int lane = threadIdx.x & 31;
    int node = (blockIdx.x * blockDim.x + threadIdx.x) >> 5;
    if (node >= N_NODES) return;
    const float* hrow = g_h + node * HID;
    const float4* wrow = (const float4*)(Wq + (size_t)node * (HID * 8));
    float acc[8] = {0, 0, 0, 0, 0, 0, 0, 0};
#pragma unroll
    for (int u = 0; u < 8; ++u) {
        int hidx = u * 32 + lane;
        float s = hrow[hidx];
        float4 w0 = __ldg(wrow + hidx * 2);
        float4 w1 = __ldg(wrow + hidx * 2 + 1);
        acc[0] = fmaf(s, w0.x, acc[0]); acc[1] = fmaf(s, w0.y, acc[1]);
        acc[2] = fmaf(s, w0.z, acc[2]); acc[3] = fmaf(s, w0.w, acc[3]);
        acc[4] = fmaf(s, w1.x, acc[4]); acc[5] = fmaf(s, w1.y, acc[5]);
        acc[6] = fmaf(s, w1.z, acc[6]); acc[7] = fmaf(s, w1.w, acc[7]);
    }
#pragma unroll
    for (int d = 16; d; d >>= 1)
#pragma unroll
        for (int i = 0; i < 8; ++i)
            acc[i] += __shfl_xor_sync(0xffffffffu, acc[i], d);
    if (lane == 0) {
#pragma unroll
        for (int i = 0; i < 8; ++i)
            out[node * 8 + i] = acc[i] + bq[node * 8 + i];
    }
}

// ---------------- launch ----------------
extern "C" void kernel_launch(void* const* d_in, const int* in_sizes, int n_in,
                              void* d_out, int out_size)
{
    const float* x  = (const float*)d_in[0];
    const void*  ei = d_in[1];
    const float* W0 = (const float*)d_in[2];
    const float* b0 = (const float*)d_in[3];
    const float* W1 = (const float*)d_in[4];
    const float* b1 = (const float*)d_in[5];
    const float* W2 = (const float*)d_in[6];
    const float* b2 = (const float*)d_in[7];
    const float* Wq = (const float*)d_in[8];
    const float* bq = (const float*)d_in[9];
    float* out = (float*)d_out;

    uint32_t dk[3][2];
    for (uint32_t i = 0; i < 3; ++i)
        threefry2x32(0u, 42u, 0u, i, &dk[i][0], &dk[i][1]);

    detect_kernel<<<1, 32>>>((const unsigned int*)ei);
    init_kernel<<<(N_NODES + 255) / 256, 256>>>();
    convert_kernel<<<(E_EDGES + 255) / 256, 256>>>(ei);
    scan_kernel<<<1, 1024>>>();
    scatter_kernel<<<(E_EDGES + 255) / 256, 256>>>();

    aggx_kernel<<<(N_NODES * 32 + 255) / 256, 256>>>(x);
    expand_l1_kernel<<<NH / 256, 256>>>(W0, b0, dk[0][0], dk[0][1]);

    gemm_kernel<<<dim3(NPAD / 128, 2), 256>>>(W1);
    agg_kernel<<<(N_NODES * 32 + 255) / 256, 256>>>(b1, dk[1][0], dk[1][1]);

    gemm_kernel<<<dim3(NPAD / 128, 2), 256>>>(W2);
    agg_kernel<<<(N_NODES * 32 + 255) / 256, 256>>>(b2, dk[2][0], dk[2][1]);

    head_kernel<<<(N_NODES * 32 + 255) / 256, 256>>>(Wq, bq, out);
}

// round 5
// speedup vs baseline: 1.2305x; 1.0664x over previous
#include <cuda_runtime.h>
#include <stdint.h>

#define N_NODES 20000
#define NPAD    20096           // 157 * 128
#define NBLK    157             // NPAD / 128
#define HID     256
#define E_EDGES 640000
#define NH      (N_NODES * HID) // 5,120,000

// ---------------- scratch (device globals; no allocation) ----------------
__device__ int   g_is64;
__device__ int   g_deg[N_NODES];
__device__ int   g_cursor[N_NODES];
__device__ int   g_rowptr[N_NODES + 1];
__device__ int   g_bsum[NBLK];
__device__ int   g_boff[NBLK];
__device__ int2  g_csr[E_EDGES];        // (src, bitcast(dinv[src]))
__device__ float g_dinv[N_NODES];
__device__ float g_aggx[N_NODES];
__device__ float g_h[NPAD * HID];       // padded rows stay zero forever
__device__ float g_t[NPAD * HID];

// ---------------- packed f32x2 helpers (sm_103a FFMA2 path) ----------------
__device__ __forceinline__ uint64_t pack2_dup(float x)
{
    uint64_t r;
    asm("mov.b64 %0, {%1, %1};" : "=l"(r) : "f"(x));
    return r;
}
__device__ __forceinline__ void fma2(uint64_t& d, uint64_t a, uint64_t b)
{
    asm("fma.rn.f32x2 %0, %1, %2, %0;" : "+l"(d) : "l"(a), "l"(b));
}
__device__ __forceinline__ float2 unpack2(uint64_t v)
{
    float2 r;
    asm("mov.b64 {%0, %1}, %2;" : "=f"(r.x), "=f"(r.y) : "l"(v));
    return r;
}

// ---------------- threefry2x32 (JAX-exact) ----------------
__host__ __device__ __forceinline__ void threefry2x32(
    uint32_t k0, uint32_t k1, uint32_t x0, uint32_t x1,
    uint32_t* o0, uint32_t* o1)
{
    uint32_t ks2 = k0 ^ k1 ^ 0x1BD11BDAu;
    x0 += k0; x1 += k1;
#define TF_R(r) { x0 += x1; x1 = (x1 << (r)) | (x1 >> (32 - (r))); x1 ^= x0; }
    TF_R(13) TF_R(15) TF_R(26) TF_R(6)
    x0 += k1; x1 += ks2 + 1u;
    TF_R(17) TF_R(29) TF_R(16) TF_R(24)
    x0 += ks2; x1 += k0 + 2u;
    TF_R(13) TF_R(15) TF_R(26) TF_R(6)
    x0 += k0; x1 += k1 + 3u;
    TF_R(17) TF_R(29) TF_R(16) TF_R(24)
    x0 += k1; x1 += ks2 + 4u;
    TF_R(13) TF_R(15) TF_R(26) TF_R(6)
    x0 += ks2; x1 += k0 + 5u;
#undef TF_R
    *o0 = x0; *o1 = x1;
}

// JAX partitionable threefry: bits32[e] = o0 ^ o1 at counter (0, e);
// keep <=> bit31 == 0; kept values scaled by 1/(1-p) = 2.
__device__ __forceinline__ float apply_dropout(float v, uint32_t k0, uint32_t k1, uint32_t e)
{
    uint32_t o0, o1;
    threefry2x32(k0, k1, 0u, e, &o0, &o1);
    return ((o0 ^ o1) & 0x80000000u) ? 0.0f : 2.0f * v;
}

// ---------------- preprocessing ----------------
__global__ void detect_kernel(const unsigned int* __restrict__ w)
{
    int lane = threadIdx.x;
    int z = (w[4 * lane + 1] == 0u) && (w[4 * lane + 3] == 0u);
    unsigned m = __ballot_sync(0xffffffffu, z);
    if (lane == 0) g_is64 = (m == 0xffffffffu);
}

__global__ void init_kernel()
{
    int i = blockIdx.x * blockDim.x + threadIdx.x;
    if (i < N_NODES) { g_deg[i] = 0; g_cursor[i] = 0; }
}

// degree histogram only (no edge copy)
__global__ void convert_kernel(const void* __restrict__ ei)
{
    int e = blockIdx.x * blockDim.x + threadIdx.x;
    if (e >= E_EDGES) return;
    int d;
    if (g_is64) d = (int)((const long long*)ei)[E_EDGES + e];
    else        d = ((const int*)ei)[E_EDGES + e];
    atomicAdd(&g_deg[d], 1);
}

// ---- scan phase 1: per-128-chunk sums + dinv (157 blocks x 128) ----
__global__ void scan_phase1()
{
    __shared__ int ws[4];
    int i = blockIdx.x * 128 + threadIdx.x;
    int v = (i < N_NODES) ? g_deg[i] : 0;
    if (i < N_NODES) g_dinv[i] = rsqrtf((float)(v + 1));  // +1 self loop
    int lane = threadIdx.x & 31, wid = threadIdx.x >> 5;
    int s = v;
#pragma unroll
    for (int d = 16; d; d >>= 1) s += __shfl_xor_sync(0xffffffffu, s, d);
    if (lane == 0) ws[wid] = s;
    __syncthreads();
    if (threadIdx.x == 0) g_bsum[blockIdx.x] = ws[0] + ws[1] + ws[2] + ws[3];
}

// ---- scan phase 2: exclusive scan of 157 block sums (1 block x 256) ----
__global__ void scan_phase2()
{
    __shared__ int ws[8];
    int t = threadIdx.x;
    int v = (t < NBLK) ? g_bsum[t] : 0;
    int lane = t & 31, wid = t >> 5;
    int s = v;
#pragma unroll
    for (int d = 1; d < 32; d <<= 1) {
        int n = __shfl_up_sync(0xffffffffu, s, d);
        if (lane >= d) s += n;
    }
    if (lane == 31) ws[wid] = s;
    __syncthreads();
    if (wid == 0 && lane < 8) {
        int w = ws[lane];
#pragma unroll
        for (int d = 1; d < 8; d <<= 1) {
            int n = __shfl_up_sync(0x000000ffu, w, d);
            if (lane >= d) w += n;
        }
        ws[lane] = w;
    }
    __syncthreads();
    int off = (s - v) + (wid ? ws[wid - 1] : 0);
    if (t < NBLK) g_boff[t] = off;
    if (t == NBLK - 1) g_rowptr[N_NODES] = off + v;
}

// ---- scan phase 3: local exclusive scan + block offset (157 blocks x 128) ----
__global__ void scan_phase3()
{
    __shared__ int ws[4];
    int i = blockIdx.x * 128 + threadIdx.x;
    int v = (i < N_NODES) ? g_deg[i] : 0;
    int lane = threadIdx.x & 31, wid = threadIdx.x >> 5;
    int s = v;
#pragma unroll
    for (int d = 1; d < 32; d <<= 1) {
        int n = __shfl_up_sync(0xffffffffu, s, d);
        if (lane >= d) s += n;
    }
    if (lane == 31) ws[wid] = s;
    __syncthreads();
    if (wid == 0 && lane < 4) {
        int w = ws[lane];
#pragma unroll
        for (int d = 1; d < 4; d <<= 1) {
            int n = __shfl_up_sync(0x0000000fu, w, d);
            if (lane >= d) w += n;
        }
        ws[lane] = w;
    }
    __syncthreads();
    if (i < N_NODES)
        g_rowptr[i] = g_boff[blockIdx.x] + (s - v) + (wid ? ws[wid - 1] : 0);
}

// scatter reads edge_index directly (no srcA/dstA intermediates)
__global__ void scatter_kernel(const void* __restrict__ ei)
{
    int e = blockIdx.x * blockDim.x + threadIdx.x;
    if (e >= E_EDGES) return;
    int s, d;
    if (g_is64) {
        const long long* p = (const long long*)ei;
        s = (int)p[e]; d = (int)p[E_EDGES + e];
    } else {
        const int* p = (const int*)ei;
        s = p[e]; d = p[E_EDGES + e];
    }
    int pos = g_rowptr[d] + atomicAdd(&g_cursor[d], 1);
    g_csr[pos] = make_int2(s, __float_as_int(g_dinv[s]));
}

// ---------------- layer 1 (Fin = 1 rewrite) ----------------
__global__ void aggx_kernel(const float* __restrict__ x)
{
    int lane = threadIdx.x & 31;
    int node = (blockIdx.x * blockDim.x + threadIdx.x) >> 5;
    if (node >= N_NODES) return;
    int s = g_rowptr[node], e_end = g_rowptr[node + 1];
    float sum = 0.0f;
    for (int e = s + lane; e < e_end; e += 32) {
        int2 sw = g_csr[e];
        sum = fmaf(__int_as_float(sw.y), __ldg(x + sw.x), sum);
    }
#pragma unroll
    for (int d = 16; d; d >>= 1) sum += __shfl_xor_sync(0xffffffffu, sum, d);
    if (lane == 0) {
        float di = g_dinv[node];
        g_aggx[node] = di * fmaf(di, __ldg(x + node), sum);
    }
}

__global__ void expand_l1_kernel(const float* __restrict__ W0,
                                 const float* __restrict__ b0,
                                 uint32_t k0, uint32_t k1)
{
    int e = blockIdx.x * blockDim.x + threadIdx.x;
    if (e >= NH) return;
    int i = e >> 8, j = e & 255;
    float v = fmaxf(fmaf(g_aggx[i], W0[j], b0[j]), 0.0f);
    g_h[e] = apply_dropout(v, k0, k1, (uint32_t)e);
}

// ---------------- GEMM: g_t = g_h @ B, k-tile 16, FFMA2 accumulation ----------------
__global__ void __launch_bounds__(256, 2) gemm_kernel(const float* __restrict__ B)
{
    __shared__ float As[16][132];
    __shared__ float Bs[16][132];
    int tid = threadIdx.x;
    int m0 = blockIdx.x * 128;
    int n0 = blockIdx.y * 128;
    int tm = (tid >> 4) * 4;   // rows {tm..tm+3} and {64+tm..}
    int tn = (tid & 15) * 4;   // cols {tn..tn+3} and {64+tn..}

    uint64_t acc[8][4];
#pragma unroll
    for (int i = 0; i < 8; ++i)
#pragma unroll
        for (int p = 0; p < 4; ++p) acc[i][p] = 0ull;

    // A loads: 128 rows x 16 k / 256 threads = 8 floats (2 float4) per thread
    int arow = tid >> 1;
    int aseg = (tid & 1) * 8;
    // B loads: 16 rows x 128 cols / 256 threads = 8 floats (2 float4) per thread
    int brow = tid >> 4;
    int bseg = (tid & 15) * 8;
    const float* Ag = g_h + (m0 + arow) * HID + aseg;
    const float* Bg = B + brow * HID + n0 + bseg;

    for (int kt = 0; kt < 256; kt += 16) {
        float4 av0 = *(const float4*)(Ag + kt);
        float4 av1 = *(const float4*)(Ag + kt + 4);
        float4 bv0 = *(const float4*)(Bg + kt * HID);
        float4 bv1 = *(const float4*)(Bg + kt * HID + 4);
        __syncthreads();
        As[aseg + 0][arow] = av0.x;
        As[aseg + 1][arow] = av0.y;
        As[aseg + 2][arow] = av0.z;
        As[aseg + 3][arow] = av0.w;
        As[aseg + 4][arow] = av1.x;
        As[aseg + 5][arow] = av1.y;
        As[aseg + 6][arow] = av1.z;
        As[aseg + 7][arow] = av1.w;
        *(float4*)&Bs[brow][bseg]     = bv0;
        *(float4*)&Bs[brow][bseg + 4] = bv1;
        __syncthreads();
#pragma unroll
        for (int k = 0; k < 16; ++k) {
            float a[8];
            *(float4*)(a)     = *(const float4*)&As[k][tm];
            *(float4*)(a + 4) = *(const float4*)&As[k][64 + tm];
            uint64_t bp[4];
            bp[0] = *(const uint64_t*)&Bs[k][tn];
            bp[1] = *(const uint64_t*)&Bs[k][tn + 2];
            bp[2] = *(const uint64_t*)&Bs[k][64 + tn];
            bp[3] = *(const uint64_t*)&Bs[k][64 + tn + 2];
#pragma unroll
            for (int i = 0; i < 8; ++i) {
                uint64_t aa = pack2_dup(a[i]);
                fma2(acc[i][0], aa, bp[0]);
                fma2(acc[i][1], aa, bp[1]);
                fma2(acc[i][2], aa, bp[2]);
                fma2(acc[i][3], aa, bp[3]);
            }
        }
    }
#pragma unroll
    for (int i = 0; i < 8; ++i) {
        int row = m0 + ((i < 4) ? (tm + i) : (64 + tm + i - 4));
        float* Cr = g_t + row * HID + n0;
        float2 p0 = unpack2(acc[i][0]);
        float2 p1 = unpack2(acc[i][1]);
        float2 p2 = unpack2(acc[i][2]);
        float2 p3 = unpack2(acc[i][3]);
        *(float4*)(Cr + tn)      = make_float4(p0.x, p0.y, p1.x, p1.y);
        *(float4*)(Cr + 64 + tn) = make_float4(p2.x, p2.y, p3.x, p3.y);
    }
}

// ---------------- aggregation + bias + relu + dropout (fused) -> g_h ----------------
__global__ void agg_kernel(const float* __restrict__ bias, uint32_t k0, uint32_t k1)
{
    int lane = threadIdx.x & 31;
    int node = (blockIdx.x * blockDim.x + threadIdx.x) >> 5;
    if (node >= N_NODES) return;
    int e = g_rowptr[node], e_end = g_rowptr[node + 1];
    float4 acc0 = make_float4(0, 0, 0, 0);
    float4 acc1 = make_float4(0, 0, 0, 0);
    const float4* T = (const float4*)g_t;
    for (; e < e_end; ++e) {
        int2 sw = g_csr[e];
        float w = __int_as_float(sw.y);
        int base = sw.x * (HID / 4);
        float4 a = __ldg(T + base + lane);
        float4 b = __ldg(T + base + 32 + lane);
        acc0.x = fmaf(w, a.x, acc0.x); acc0.y = fmaf(w, a.y, acc0.y);
        acc0.z = fmaf(w, a.z, acc0.z); acc0.w = fmaf(w, a.w, acc0.w);
        acc1.x = fmaf(w, b.x, acc1.x); acc1.y = fmaf(w, b.y, acc1.y);
        acc1.z = fmaf(w, b.z, acc1.z); acc1.w = fmaf(w, b.w, acc1.w);
    }
    float di = g_dinv[node];
    int base = node * (HID / 4);
    {   // self loop
        float4 a = __ldg(T + base + lane);
        float4 b = __ldg(T + base + 32 + lane);
        acc0.x = fmaf(di, a.x, acc0.x); acc0.y = fmaf(di, a.y, acc0.y);
        acc0.z = fmaf(di, a.z, acc0.z); acc0.w = fmaf(di, a.w, acc0.w);
        acc1.x = fmaf(di, b.x, acc1.x); acc1.y = fmaf(di, b.y, acc1.y);
        acc1.z = fmaf(di, b.z, acc1.z); acc1.w = fmaf(di, b.w, acc1.w);
    }
    float4 bb0 = *(const float4*)(bias + lane * 4);
    float4 bb1 = *(const float4*)(bias + 128 + lane * 4);
    float4 o0, o1;
    o0.x = fmaxf(fmaf(acc0.x, di, bb0.x), 0.0f);
    o0.y = fmaxf(fmaf(acc0.y, di, bb0.y), 0.0f);
    o0.z = fmaxf(fmaf(acc0.z, di, bb0.z), 0.0f);
    o0.w = fmaxf(fmaf(acc0.w, di, bb0.w), 0.0f);
    o1.x = fmaxf(fmaf(acc1.x, di, bb1.x), 0.0f);
    o1.y = fmaxf(fmaf(acc1.y, di, bb1.y), 0.0f);
    o1.z = fmaxf(fmaf(acc1.z, di, bb1.z), 0.0f);
    o1.w = fmaxf(fmaf(acc1.w, di, bb1.w), 0.0f);
    uint32_t e0 = (uint32_t)(node * HID + lane * 4);
    uint32_t e1 = e0 + 128;
    o0.x = apply_dropout(o0.x, k0, k1, e0 + 0);
    o0.y = apply_dropout(o0.y, k0, k1, e0 + 1);
    o0.z = apply_dropout(o0.z, k0, k1, e0 + 2);
    o0.w = apply_dropout(o0.w, k0, k1, e0 + 3);
    o1.x = apply_dropout(o1.x, k0, k1, e1 + 0);
    o1.y = apply_dropout(o1.y, k0, k1, e1 + 1);
    o1.z = apply_dropout(o1.z, k0, k1, e1 + 2);
    o1.w = apply_dropout(o1.w, k0, k1, e1 + 3);
    float4* H = (float4*)g_h;
    H[base + lane] = o0;
    H[base + 32 + lane] = o1;
}

// ---------------- per-node heads ----------------
__global__ void head_kernel(const float* __restrict__ Wq,
                            const float* __restrict__ bq,
                            float* __restrict__ out)
{
    int lane = threadIdx.x & 31;
    int node = (blockIdx.x * blockDim.x + threadIdx.x) >> 5;
    if (node >= N_NODES) return;
    const float* hrow = g_h + node * HID;
    const float4* wrow = (const float4*)(Wq + (size_t)node * (HID * 8));
    float acc[8] = {0, 0, 0, 0, 0, 0, 0, 0};
#pragma unroll
    for (int u = 0; u < 8; ++u) {
        int hidx = u * 32 + lane;
        float s = hrow[hidx];
        float4 w0 = __ldg(wrow + hidx * 2);
        float4 w1 = __ldg(wrow + hidx * 2 + 1);
        acc[0] = fmaf(s, w0.x, acc[0]); acc[1] = fmaf(s, w0.y, acc[1]);
        acc[2] = fmaf(s, w0.z, acc[2]); acc[3] = fmaf(s, w0.w, acc[3]);
        acc[4] = fmaf(s, w1.x, acc[4]); acc[5] = fmaf(s, w1.y, acc[5]);
        acc[6] = fmaf(s, w1.z, acc[6]); acc[7] = fmaf(s, w1.w, acc[7]);
    }
#pragma unroll
    for (int d = 16; d; d >>= 1)
#pragma unroll
        for (int i = 0; i < 8; ++i)
            acc[i] += __shfl_xor_sync(0xffffffffu, acc[i], d);
    if (lane == 0) {
#pragma unroll
        for (int i = 0; i < 8; ++i)
            out[node * 8 + i] = acc[i] + bq[node * 8 + i];
    }
}

// ---------------- launch ----------------
extern "C" void kernel_launch(void* const* d_in, const int* in_sizes, int n_in,
                              void* d_out, int out_size)
{
    const float* x  = (const float*)d_in[0];
    const void*  ei = d_in[1];
    const float* W0 = (const float*)d_in[2];
    const float* b0 = (const float*)d_in[3];
    const float* W1 = (const float*)d_in[4];
    const float* b1 = (const float*)d_in[5];
    const float* W2 = (const float*)d_in[6];
    const float* b2 = (const float*)d_in[7];
    const float* Wq = (const float*)d_in[8];
    const float* bq = (const float*)d_in[9];
    float* out = (float*)d_out;

    uint32_t dk[3][2];
    for (uint32_t i = 0; i < 3; ++i)
        threefry2x32(0u, 42u, 0u, i, &dk[i][0], &dk[i][1]);

    detect_kernel<<<1, 32>>>((const unsigned int*)ei);
    init_kernel<<<(N_NODES + 255) / 256, 256>>>();
    convert_kernel<<<(E_EDGES + 255) / 256, 256>>>(ei);
    scan_phase1<<<NBLK, 128>>>();
    scan_phase2<<<1, 256>>>();
    scan_phase3<<<NBLK, 128>>>();
    scatter_kernel<<<(E_EDGES + 255) / 256, 256>>>(ei);

    aggx_kernel<<<(N_NODES * 32 + 255) / 256, 256>>>(x);
    expand_l1_kernel<<<NH / 256, 256>>>(W0, b0, dk[0][0], dk[0][1]);

    gemm_kernel<<<dim3(NPAD / 128, 2), 256>>>(W1);
    agg_kernel<<<(N_NODES * 32 + 255) / 256, 256>>>(b1, dk[1][0], dk[1][1]);

    gemm_kernel<<<dim3(NPAD / 128, 2), 256>>>(W2);
    agg_kernel<<<(N_NODES * 32 + 255) / 256, 256>>>(b2, dk[2][0], dk[2][1]);

    head_kernel<<<(N_NODES * 32 + 255) / 256, 256>>>(Wq, bq, out);
}

// round 6
// speedup vs baseline: 1.2962x; 1.0534x over previous
#include <cuda_runtime.h>
#include <cuda_fp16.h>
#include <stdint.h>

#define N_NODES 20000
#define NPAD    20096           // 157 * 128
#define NBLK    157             // NPAD / 128
#define HID     256
#define E_EDGES 640000
#define NH      (N_NODES * HID) // 5,120,000

// ---------------- scratch (device globals; no allocation) ----------------
__device__ int    g_is64;
__device__ int    g_deg[N_NODES];
__device__ int    g_cursor[N_NODES];
__device__ int    g_rowptr[N_NODES + 1];
__device__ int    g_bsum[NBLK];
__device__ int    g_boff[NBLK];
__device__ int2   g_csr[E_EDGES];       // (src, bitcast(dinv[src]))
__device__ float  g_dinv[N_NODES];
__device__ float  g_aggx[N_NODES];
__device__ float  g_h[NPAD * HID];      // padded rows stay zero forever
__device__ __half g_t[NPAD * HID];      // fp16 GEMM output (gather payload)

// ---------------- packed f32x2 helpers (sm_103a FFMA2 path) ----------------
__device__ __forceinline__ uint64_t pack2_dup(float x)
{
    uint64_t r;
    asm("mov.b64 %0, {%1, %1};" : "=l"(r) : "f"(x));
    return r;
}
__device__ __forceinline__ void fma2(uint64_t& d, uint64_t a, uint64_t b)
{
    asm("fma.rn.f32x2 %0, %1, %2, %0;" : "+l"(d) : "l"(a), "l"(b));
}
__device__ __forceinline__ float2 unpack2(uint64_t v)
{
    float2 r;
    asm("mov.b64 {%0, %1}, %2;" : "=f"(r.x), "=f"(r.y) : "l"(v));
    return r;
}

// ---------------- threefry2x32 (JAX-exact) ----------------
__host__ __device__ __forceinline__ void threefry2x32(
    uint32_t k0, uint32_t k1, uint32_t x0, uint32_t x1,
    uint32_t* o0, uint32_t* o1)
{
    uint32_t ks2 = k0 ^ k1 ^ 0x1BD11BDAu;
    x0 += k0; x1 += k1;
#define TF_R(r) { x0 += x1; x1 = (x1 << (r)) | (x1 >> (32 - (r))); x1 ^= x0; }
    TF_R(13) TF_R(15) TF_R(26) TF_R(6)
    x0 += k1; x1 += ks2 + 1u;
    TF_R(17) TF_R(29) TF_R(16) TF_R(24)
    x0 += ks2; x1 += k0 + 2u;
    TF_R(13) TF_R(15) TF_R(26) TF_R(6)
    x0 += k0; x1 += k1 + 3u;
    TF_R(17) TF_R(29) TF_R(16) TF_R(24)
    x0 += k1; x1 += ks2 + 4u;
    TF_R(13) TF_R(15) TF_R(26) TF_R(6)
    x0 += ks2; x1 += k0 + 5u;
#undef TF_R
    *o0 = x0; *o1 = x1;
}

// JAX partitionable threefry: bits32[e] = o0 ^ o1 at counter (0, e);
// keep <=> bit31 == 0; kept values scaled by 1/(1-p) = 2.
__device__ __forceinline__ float apply_dropout(float v, uint32_t k0, uint32_t k1, uint32_t e)
{
    uint32_t o0, o1;
    threefry2x32(k0, k1, 0u, e, &o0, &o1);
    return ((o0 ^ o1) & 0x80000000u) ? 0.0f : 2.0f * v;
}

// ---------------- preprocessing ----------------
__global__ void detect_kernel(const unsigned int* __restrict__ w)
{
    int lane = threadIdx.x;
    int z = (w[4 * lane + 1] == 0u) && (w[4 * lane + 3] == 0u);
    unsigned m = __ballot_sync(0xffffffffu, z);
    if (lane == 0) g_is64 = (m == 0xffffffffu);
}

__global__ void init_kernel()
{
    int i = blockIdx.x * blockDim.x + threadIdx.x;
    if (i < N_NODES) { g_deg[i] = 0; g_cursor[i] = 0; }
}

__global__ void convert_kernel(const void* __restrict__ ei)
{
    int e = blockIdx.x * blockDim.x + threadIdx.x;
    if (e >= E_EDGES) return;
    int d;
    if (g_is64) d = (int)((const long long*)ei)[E_EDGES + e];
    else        d = ((const int*)ei)[E_EDGES + e];
    atomicAdd(&g_deg[d], 1);
}

__global__ void scan_phase1()
{
    __shared__ int ws[4];
    int i = blockIdx.x * 128 + threadIdx.x;
    int v = (i < N_NODES) ? g_deg[i] : 0;
    if (i < N_NODES) g_dinv[i] = rsqrtf((float)(v + 1));  // +1 self loop
    int lane = threadIdx.x & 31, wid = threadIdx.x >> 5;
    int s = v;
#pragma unroll
    for (int d = 16; d; d >>= 1) s += __shfl_xor_sync(0xffffffffu, s, d);
    if (lane == 0) ws[wid] = s;
    __syncthreads();
    if (threadIdx.x == 0) g_bsum[blockIdx.x] = ws[0] + ws[1] + ws[2] + ws[3];
}

__global__ void scan_phase2()
{
    __shared__ int ws[8];
    int t = threadIdx.x;
    int v = (t < NBLK) ? g_bsum[t] : 0;
    int lane = t & 31, wid = t >> 5;
    int s = v;
#pragma unroll
    for (int d = 1; d < 32; d <<= 1) {
        int n = __shfl_up_sync(0xffffffffu, s, d);
        if (lane >= d) s += n;
    }
    if (lane == 31) ws[wid] = s;
    __syncthreads();
    if (wid == 0 && lane < 8) {
        int w = ws[lane];
#pragma unroll
        for (int d = 1; d < 8; d <<= 1) {
            int n = __shfl_up_sync(0x000000ffu, w, d);
            if (lane >= d) w += n;
        }
        ws[lane] = w;
    }
    __syncthreads();
    int off = (s - v) + (wid ? ws[wid - 1] : 0);
    if (t < NBLK) g_boff[t] = off;
    if (t == NBLK - 1) g_rowptr[N_NODES] = off + v;
}

__global__ void scan_phase3()
{
    __shared__ int ws[4];
    int i = blockIdx.x * 128 + threadIdx.x;
    int v = (i < N_NODES) ? g_deg[i] : 0;
    int lane = threadIdx.x & 31, wid = threadIdx.x >> 5;
    int s = v;
#pragma unroll
    for (int d = 1; d < 32; d <<= 1) {
        int n = __shfl_up_sync(0xffffffffu, s, d);
        if (lane >= d) s += n;
    }
    if (lane == 31) ws[wid] = s;
    __syncthreads();
    if (wid == 0 && lane < 4) {
        int w = ws[lane];
#pragma unroll
        for (int d = 1; d < 4; d <<= 1) {
            int n = __shfl_up_sync(0x0000000fu, w, d);
            if (lane >= d) w += n;
        }
        ws[lane] = w;
    }
    __syncthreads();
    if (i < N_NODES)
        g_rowptr[i] = g_boff[blockIdx.x] + (s - v) + (wid ? ws[wid - 1] : 0);
}

__global__ void scatter_kernel(const void* __restrict__ ei)
{
    int e = blockIdx.x * blockDim.x + threadIdx.x;
    if (e >= E_EDGES) return;
    int s, d;
    if (g_is64) {
        const long long* p = (const long long*)ei;
        s = (int)p[e]; d = (int)p[E_EDGES + e];
    } else {
        const int* p = (const int*)ei;
        s = p[e]; d = p[E_EDGES + e];
    }
    int pos = g_rowptr[d] + atomicAdd(&g_cursor[d], 1);
    g_csr[pos] = make_int2(s, __float_as_int(g_dinv[s]));
}

// ---------------- layer 1 (Fin = 1 rewrite) ----------------
__global__ void aggx_kernel(const float* __restrict__ x)
{
    int lane = threadIdx.x & 31;
    int node = (blockIdx.x * blockDim.x + threadIdx.x) >> 5;
    if (node >= N_NODES) return;
    int s = g_rowptr[node], e_end = g_rowptr[node + 1];
    float sum = 0.0f;
    for (int e = s + lane; e < e_end; e += 32) {
        int2 sw = g_csr[e];
        sum = fmaf(__int_as_float(sw.y), __ldg(x + sw.x), sum);
    }
#pragma unroll
    for (int d = 16; d; d >>= 1) sum += __shfl_xor_sync(0xffffffffu, sum, d);
    if (lane == 0) {
        float di = g_dinv[node];
        g_aggx[node] = di * fmaf(di, __ldg(x + node), sum);
    }
}

__global__ void expand_l1_kernel(const float* __restrict__ W0,
                                 const float* __restrict__ b0,
                                 uint32_t k0, uint32_t k1)
{
    int e = blockIdx.x * blockDim.x + threadIdx.x;
    if (e >= NH) return;
    int i = e >> 8, j = e & 255;
    float v = fmaxf(fmaf(g_aggx[i], W0[j], b0[j]), 0.0f);
    g_h[e] = apply_dropout(v, k0, k1, (uint32_t)e);
}

// ---------------- GEMM: g_t(fp16) = g_h @ B, k-tile 16, FFMA2 ----------------
__global__ void __launch_bounds__(256, 2) gemm_kernel(const float* __restrict__ B)
{
    __shared__ float As[16][132];
    __shared__ float Bs[16][132];
    int tid = threadIdx.x;
    int m0 = blockIdx.x * 128;
    int n0 = blockIdx.y * 128;
    int tm = (tid >> 4) * 4;   // rows {tm..tm+3} and {64+tm..}
    int tn = (tid & 15) * 4;   // cols {tn..tn+3} and {64+tn..}

    uint64_t acc[8][4];
#pragma unroll
    for (int i = 0; i < 8; ++i)
#pragma unroll
        for (int p = 0; p < 4; ++p) acc[i][p] = 0ull;

    int arow = tid >> 1;
    int aseg = (tid & 1) * 8;
    int brow = tid >> 4;
    int bseg = (tid & 15) * 8;
    const float* Ag = g_h + (m0 + arow) * HID + aseg;
    const float* Bg = B + brow * HID + n0 + bseg;

    for (int kt = 0; kt < 256; kt += 16) {
        float4 av0 = *(const float4*)(Ag + kt);
        float4 av1 = *(const float4*)(Ag + kt + 4);
        float4 bv0 = *(const float4*)(Bg + kt * HID);
        float4 bv1 = *(const float4*)(Bg + kt * HID + 4);
        __syncthreads();
        As[aseg + 0][arow] = av0.x;
        As[aseg + 1][arow] = av0.y;
        As[aseg + 2][arow] = av0.z;
        As[aseg + 3][arow] = av0.w;
        As[aseg + 4][arow] = av1.x;
        As[aseg + 5][arow] = av1.y;
        As[aseg + 6][arow] = av1.z;
        As[aseg + 7][arow] = av1.w;
        *(float4*)&Bs[brow][bseg]     = bv0;
        *(float4*)&Bs[brow][bseg + 4] = bv1;
        __syncthreads();
#pragma unroll
        for (int k = 0; k < 16; ++k) {
            float a[8];
            *(float4*)(a)     = *(const float4*)&As[k][tm];
            *(float4*)(a + 4) = *(const float4*)&As[k][64 + tm];
            uint64_t bp[4];
            bp[0] = *(const uint64_t*)&Bs[k][tn];
            bp[1] = *(const uint64_t*)&Bs[k][tn + 2];
            bp[2] = *(const uint64_t*)&Bs[k][64 + tn];
            bp[3] = *(const uint64_t*)&Bs[k][64 + tn + 2];
#pragma unroll
            for (int i = 0; i < 8; ++i) {
                uint64_t aa = pack2_dup(a[i]);
                fma2(acc[i][0], aa, bp[0]);
                fma2(acc[i][1], aa, bp[1]);
                fma2(acc[i][2], aa, bp[2]);
                fma2(acc[i][3], aa, bp[3]);
            }
        }
    }
#pragma unroll
    for (int i = 0; i < 8; ++i) {
        int row = m0 + ((i < 4) ? (tm + i) : (64 + tm + i - 4));
        __half* Cr = g_t + row * HID + n0;
        float2 p0 = unpack2(acc[i][0]);
        float2 p1 = unpack2(acc[i][1]);
        float2 p2 = unpack2(acc[i][2]);
        float2 p3 = unpack2(acc[i][3]);
        __half2 h0 = __floats2half2_rn(p0.x, p0.y);
        __half2 h1 = __floats2half2_rn(p1.x, p1.y);
        __half2 h2 = __floats2half2_rn(p2.x, p2.y);
        __half2 h3 = __floats2half2_rn(p3.x, p3.y);
        *(uint2*)(Cr + tn)      = make_uint2(*(uint32_t*)&h0, *(uint32_t*)&h1);
        *(uint2*)(Cr + 64 + tn) = make_uint2(*(uint32_t*)&h2, *(uint32_t*)&h3);
    }
}

// ---------------- aggregation + bias + relu + dropout (fused) -> g_h ----------------
// lane handles 8 contiguous channels [lane*8, lane*8+8); per-edge read = one uint4 (8 fp16)
__global__ void agg_kernel(const float* __restrict__ bias, uint32_t k0, uint32_t k1)
{
    int lane = threadIdx.x & 31;
    int node = (blockIdx.x * blockDim.x + threadIdx.x) >> 5;
    if (node >= N_NODES) return;
    int e = g_rowptr[node], e_end = g_rowptr[node + 1];
    float acc[8] = {0, 0, 0, 0, 0, 0, 0, 0};
    const uint4* T = (const uint4*)g_t;   // 8 halves per uint4; row = 32 uint4
    for (; e < e_end; ++e) {
        int2 sw = g_csr[e];
        float w = __int_as_float(sw.y);
        uint4 v = __ldg(T + sw.x * (HID / 8) + lane);
        float2 f0 = __half22float2(*(__half2*)&v.x);
        float2 f1 = __half22float2(*(__half2*)&v.y);
        float2 f2 = __half22float2(*(__half2*)&v.z);
        float2 f3 = __half22float2(*(__half2*)&v.w);
        acc[0] = fmaf(w, f0.x, acc[0]); acc[1] = fmaf(w, f0.y, acc[1]);
        acc[2] = fmaf(w, f1.x, acc[2]); acc[3] = fmaf(w, f1.y, acc[3]);
        acc[4] = fmaf(w, f2.x, acc[4]); acc[5] = fmaf(w, f2.y, acc[5]);
        acc[6] = fmaf(w, f3.x, acc[6]); acc[7] = fmaf(w, f3.y, acc[7]);
    }
    float di = g_dinv[node];
    {   // self loop
        uint4 v = __ldg(T + node * (HID / 8) + lane);
        float2 f0 = __half22float2(*(__half2*)&v.x);
        float2 f1 = __half22float2(*(__half2*)&v.y);
        float2 f2 = __half22float2(*(__half2*)&v.z);
        float2 f3 = __half22float2(*(__half2*)&v.w);
        acc[0] = fmaf(di, f0.x, acc[0]); acc[1] = fmaf(di, f0.y, acc[1]);
        acc[2] = fmaf(di, f1.x, acc[2]); acc[3] = fmaf(di, f1.y, acc[3]);
        acc[4] = fmaf(di, f2.x, acc[4]); acc[5] = fmaf(di, f2.y, acc[5]);
        acc[6] = fmaf(di, f3.x, acc[6]); acc[7] = fmaf(di, f3.y, acc[7]);
    }
    float4 bb0 = *(const float4*)(bias + lane * 8);
    float4 bb1 = *(const float4*)(bias + lane * 8 + 4);
    float o[8];
    o[0] = fmaxf(fmaf(acc[0], di, bb0.x), 0.0f);
    o[1] = fmaxf(fmaf(acc[1], di, bb0.y), 0.0f);
    o[2] = fmaxf(fmaf(acc[2], di, bb0.z), 0.0f);
    o[3] = fmaxf(fmaf(acc[3], di, bb0.w), 0.0f);
    o[4] = fmaxf(fmaf(acc[4], di, bb1.x), 0.0f);
    o[5] = fmaxf(fmaf(acc[5], di, bb1.y), 0.0f);
    o[6] = fmaxf(fmaf(acc[6], di, bb1.z), 0.0f);
    o[7] = fmaxf(fmaf(acc[7], di, bb1.w), 0.0f);
    uint32_t e0 = (uint32_t)(node * HID + lane * 8);
#pragma unroll
    for (int j = 0; j < 8; ++j)
        o[j] = apply_dropout(o[j], k0, k1, e0 + j);
    float* H = g_h + node * HID + lane * 8;
    *(float4*)(H)     = make_float4(o[0], o[1], o[2], o[3]);
    *(float4*)(H + 4) = make_float4(o[4], o[5], o[6], o[7]);
}

// ---------------- per-node heads ----------------
__global__ void head_kernel(const float* __restrict__ Wq,
                            const float* __restrict__ bq,
                            float* __restrict__ out)
{
    int lane = threadIdx.x & 31;
    int node = (blockIdx.x * blockDim.x + threadIdx.x) >> 5;
    if (node >= N_NODES) return;
    const float* hrow = g_h + node * HID;
    const float4* wrow = (const float4*)(Wq + (size_t)node * (HID * 8));
    float acc[8] = {0, 0, 0, 0, 0, 0, 0, 0};
#pragma unroll
    for (int u = 0; u < 8; ++u) {
        int hidx = u * 32 + lane;
        float s = hrow[hidx];
        float4 w0 = __ldg(wrow + hidx * 2);
        float4 w1 = __ldg(wrow + hidx * 2 + 1);
        acc[0] = fmaf(s, w0.x, acc[0]); acc[1] = fmaf(s, w0.y, acc[1]);
        acc[2] = fmaf(s, w0.z, acc[2]); acc[3] = fmaf(s, w0.w, acc[3]);
        acc[4] = fmaf(s, w1.x, acc[4]); acc[5] = fmaf(s, w1.y, acc[5]);
        acc[6] = fmaf(s, w1.z, acc[6]); acc[7] = fmaf(s, w1.w, acc[7]);
    }
#pragma unroll
    for (int d = 16; d; d >>= 1)
#pragma unroll
        for (int i = 0; i < 8; ++i)
            acc[i] += __shfl_xor_sync(0xffffffffu, acc[i], d);
    if (lane == 0) {
#pragma unroll
        for (int i = 0; i < 8; ++i)
            out[node * 8 + i] = acc[i] + bq[node * 8 + i];
    }
}

// ---------------- launch ----------------
extern "C" void kernel_launch(void* const* d_in, const int* in_sizes, int n_in,
                              void* d_out, int out_size)
{
    const float* x  = (const float*)d_in[0];
    const void*  ei = d_in[1];
    const float* W0 = (const float*)d_in[2];
    const float* b0 = (const float*)d_in[3];
    const float* W1 = (const float*)d_in[4];
    const float* b1 = (const float*)d_in[5];
    const float* W2 = (const float*)d_in[6];
    const float* b2 = (const float*)d_in[7];
    const float* Wq = (const float*)d_in[8];
    const float* bq = (const float*)d_in[9];
    float* out = (float*)d_out;

    uint32_t dk[3][2];
    for (uint32_t i = 0; i < 3; ++i)
        threefry2x32(0u, 42u, 0u, i, &dk[i][0], &dk[i][1]);

    detect_kernel<<<1, 32>>>((const unsigned int*)ei);
    init_kernel<<<(N_NODES + 255) / 256, 256>>>();
    convert_kernel<<<(E_EDGES + 255) / 256, 256>>>(ei);
    scan_phase1<<<NBLK, 128>>>();
    scan_phase2<<<1, 256>>>();
    scan_phase3<<<NBLK, 128>>>();
    scatter_kernel<<<(E_EDGES + 255) / 256, 256>>>(ei);

    aggx_kernel<<<(N_NODES * 32 + 255) / 256, 256>>>(x);
    expand_l1_kernel<<<NH / 256, 256>>>(W0, b0, dk[0][0], dk[0][1]);

    gemm_kernel<<<dim3(NPAD / 128, 2), 256>>>(W1);
    agg_kernel<<<(N_NODES * 32 + 255) / 256, 256>>>(b1, dk[1][0], dk[1][1]);

    gemm_kernel<<<dim3(NPAD / 128, 2), 256>>>(W2);
    agg_kernel<<<(N_NODES * 32 + 255) / 256, 256>>>(b2, dk[2][0], dk[2][1]);

    head_kernel<<<(N_NODES * 32 + 255) / 256, 256>>>(Wq, bq, out);
}

// round 7
// speedup vs baseline: 2.0722x; 1.5987x over previous
#include <cuda_runtime.h>
#include <cuda_fp16.h>
#include <stdint.h>

#define N_NODES 20000
#define NPAD    20096           // 157 * 128
#define NBLK    157             // NPAD / 128
#define HID     256
#define E_EDGES 640000
#define NH      (N_NODES * HID) // 5,120,000

// ---------------- scratch (device globals; no allocation) ----------------
__device__ int    g_is64;
__device__ int    g_deg[N_NODES];
__device__ int    g_cursor[N_NODES];
__device__ int    g_rowptr[N_NODES + 1];
__device__ int    g_bsum[NBLK];
__device__ int    g_boff[NBLK];
__device__ int2   g_csr[E_EDGES];       // (src, bitcast(dinv[src]))
__device__ float  g_dinv[N_NODES];
__device__ float  g_aggx[N_NODES];
__device__ __half g_h[NPAD * HID];      // fp16 activations (pad rows stay zero)
__device__ __half g_t[NPAD * HID];      // fp16 GEMM output (gather payload)
__device__ __half g_wh[HID * HID];      // fp16 weight scratch

// ---------------- mma/ldmatrix helpers ----------------
__device__ __forceinline__ void ldsm_x4(uint32_t (&r)[4], uint32_t addr)
{
    asm volatile("ldmatrix.sync.aligned.m8n8.x4.shared.b16 {%0,%1,%2,%3}, [%4];"
        : "=r"(r[0]), "=r"(r[1]), "=r"(r[2]), "=r"(r[3]) : "r"(addr));
}
__device__ __forceinline__ void ldsm_x2_trans(uint32_t (&r)[2], uint32_t addr)
{
    asm volatile("ldmatrix.sync.aligned.m8n8.x2.trans.shared.b16 {%0,%1}, [%2];"
        : "=r"(r[0]), "=r"(r[1]) : "r"(addr));
}
__device__ __forceinline__ void mma16816(float (&c)[4], const uint32_t (&a)[4], const uint32_t (&b)[2])
{
    asm volatile("mma.sync.aligned.m16n8k16.row.col.f32.f16.f16.f32 "
        "{%0,%1,%2,%3}, {%4,%5,%6,%7}, {%8,%9}, {%0,%1,%2,%3};"
        : "+f"(c[0]), "+f"(c[1]), "+f"(c[2]), "+f"(c[3])
        : "r"(a[0]), "r"(a[1]), "r"(a[2]), "r"(a[3]), "r"(b[0]), "r"(b[1]));
}

// ---------------- threefry2x32 (JAX-exact) ----------------
__host__ __device__ __forceinline__ void threefry2x32(
    uint32_t k0, uint32_t k1, uint32_t x0, uint32_t x1,
    uint32_t* o0, uint32_t* o1)
{
    uint32_t ks2 = k0 ^ k1 ^ 0x1BD11BDAu;
    x0 += k0; x1 += k1;
#define TF_R(r) { x0 += x1; x1 = (x1 << (r)) | (x1 >> (32 - (r))); x1 ^= x0; }
    TF_R(13) TF_R(15) TF_R(26) TF_R(6)
    x0 += k1; x1 += ks2 + 1u;
    TF_R(17) TF_R(29) TF_R(16) TF_R(24)
    x0 += ks2; x1 += k0 + 2u;
    TF_R(13) TF_R(15) TF_R(26) TF_R(6)
    x0 += k0; x1 += k1 + 3u;
    TF_R(17) TF_R(29) TF_R(16) TF_R(24)
    x0 += k1; x1 += ks2 + 4u;
    TF_R(13) TF_R(15) TF_R(26) TF_R(6)
    x0 += ks2; x1 += k0 + 5u;
#undef TF_R
    *o0 = x0; *o1 = x1;
}

// JAX partitionable threefry: bits32[e] = o0 ^ o1 at counter (0, e);
// keep <=> bit31 == 0; kept values scaled by 1/(1-p) = 2.
__device__ __forceinline__ float apply_dropout(float v, uint32_t k0, uint32_t k1, uint32_t e)
{
    uint32_t o0, o1;
    threefry2x32(k0, k1, 0u, e, &o0, &o1);
    return ((o0 ^ o1) & 0x80000000u) ? 0.0f : 2.0f * v;
}

// ---------------- preprocessing ----------------
__global__ void detect_kernel(const unsigned int* __restrict__ w)
{
    int lane = threadIdx.x;
    int z = (w[4 * lane + 1] == 0u) && (w[4 * lane + 3] == 0u);
    unsigned m = __ballot_sync(0xffffffffu, z);
    if (lane == 0) g_is64 = (m == 0xffffffffu);
}

__global__ void init_kernel()
{
    int i = blockIdx.x * blockDim.x + threadIdx.x;
    if (i < N_NODES) { g_deg[i] = 0; g_cursor[i] = 0; }
}

__global__ void convert_kernel(const void* __restrict__ ei)
{
    int e = blockIdx.x * blockDim.x + threadIdx.x;
    if (e >= E_EDGES) return;
    int d;
    if (g_is64) d = (int)((const long long*)ei)[E_EDGES + e];
    else        d = ((const int*)ei)[E_EDGES + e];
    atomicAdd(&g_deg[d], 1);
}

__global__ void scan_phase1()
{
    __shared__ int ws[4];
    int i = blockIdx.x * 128 + threadIdx.x;
    int v = (i < N_NODES) ? g_deg[i] : 0;
    if (i < N_NODES) g_dinv[i] = rsqrtf((float)(v + 1));  // +1 self loop
    int lane = threadIdx.x & 31, wid = threadIdx.x >> 5;
    int s = v;
#pragma unroll
    for (int d = 16; d; d >>= 1) s += __shfl_xor_sync(0xffffffffu, s, d);
    if (lane == 0) ws[wid] = s;
    __syncthreads();
    if (threadIdx.x == 0) g_bsum[blockIdx.x] = ws[0] + ws[1] + ws[2] + ws[3];
}

__global__ void scan_phase2()
{
    __shared__ int ws[8];
    int t = threadIdx.x;
    int v = (t < NBLK) ? g_bsum[t] : 0;
    int lane = t & 31, wid = t >> 5;
    int s = v;
#pragma unroll
    for (int d = 1; d < 32; d <<= 1) {
        int n = __shfl_up_sync(0xffffffffu, s, d);
        if (lane >= d) s += n;
    }
    if (lane == 31) ws[wid] = s;
    __syncthreads();
    if (wid == 0 && lane < 8) {
        int w = ws[lane];
#pragma unroll
        for (int d = 1; d < 8; d <<= 1) {
            int n = __shfl_up_sync(0x000000ffu, w, d);
            if (lane >= d) w += n;
        }
        ws[lane] = w;
    }
    __syncthreads();
    int off = (s - v) + (wid ? ws[wid - 1] : 0);
    if (t < NBLK) g_boff[t] = off;
    if (t == NBLK - 1) g_rowptr[N_NODES] = off + v;
}

__global__ void scan_phase3()
{
    __shared__ int ws[4];
    int i = blockIdx.x * 128 + threadIdx.x;
    int v = (i < N_NODES) ? g_deg[i] : 0;
    int lane = threadIdx.x & 31, wid = threadIdx.x >> 5;
    int s = v;
#pragma unroll
    for (int d = 1; d < 32; d <<= 1) {
        int n = __shfl_up_sync(0xffffffffu, s, d);
        if (lane >= d) s += n;
    }
    if (lane == 31) ws[wid] = s;
    __syncthreads();
    if (wid == 0 && lane < 4) {
        int w = ws[lane];
#pragma unroll
        for (int d = 1; d < 4; d <<= 1) {
            int n = __shfl_up_sync(0x0000000fu, w, d);
            if (lane >= d) w += n;
        }
        ws[lane] = w;
    }
    __syncthreads();
    if (i < N_NODES)
        g_rowptr[i] = g_boff[blockIdx.x] + (s - v) + (wid ? ws[wid - 1] : 0);
}

__global__ void scatter_kernel(const void* __restrict__ ei)
{
    int e = blockIdx.x * blockDim.x + threadIdx.x;
    if (e >= E_EDGES) return;
    int s, d;
    if (g_is64) {
        const long long* p = (const long long*)ei;
        s = (int)p[e]; d = (int)p[E_EDGES + e];
    } else {
        const int* p = (const int*)ei;
        s = p[e]; d = p[E_EDGES + e];
    }
    int pos = g_rowptr[d] + atomicAdd(&g_cursor[d], 1);
    g_csr[pos] = make_int2(s, __float_as_int(g_dinv[s]));
}

// ---------------- weight fp32 -> fp16 ----------------
__global__ void convert_w_kernel(const float* __restrict__ W)
{
    int i = (blockIdx.x * 256 + threadIdx.x) * 4;
    float4 v = *(const float4*)(W + i);
    __half2 a = __floats2half2_rn(v.x, v.y);
    __half2 b = __floats2half2_rn(v.z, v.w);
    *(uint2*)(g_wh + i) = make_uint2(*(uint32_t*)&a, *(uint32_t*)&b);
}

// ---------------- layer 1 (Fin = 1 rewrite) ----------------
__global__ void aggx_kernel(const float* __restrict__ x)
{
    int lane = threadIdx.x & 31;
    int node = (blockIdx.x * blockDim.x + threadIdx.x) >> 5;
    if (node >= N_NODES) return;
    int s = g_rowptr[node], e_end = g_rowptr[node + 1];
    float sum = 0.0f;
    for (int e = s + lane; e < e_end; e += 32) {
        int2 sw = g_csr[e];
        sum = fmaf(__int_as_float(sw.y), __ldg(x + sw.x), sum);
    }
#pragma unroll
    for (int d = 16; d; d >>= 1) sum += __shfl_xor_sync(0xffffffffu, sum, d);
    if (lane == 0) {
        float di = g_dinv[node];
        g_aggx[node] = di * fmaf(di, __ldg(x + node), sum);
    }
}

// writes 4 elems/thread as 2 half2
__global__ void expand_l1_kernel(const float* __restrict__ W0,
                                 const float* __restrict__ b0,
                                 uint32_t k0, uint32_t k1)
{
    int idx = blockIdx.x * blockDim.x + threadIdx.x;
    if (idx >= NH / 4) return;
    int e4 = idx * 4;
    int i = e4 >> 8, j = e4 & 255;
    float a = g_aggx[i];
    float4 w = *(const float4*)(W0 + j);
    float4 b = *(const float4*)(b0 + j);
    float v0 = apply_dropout(fmaxf(fmaf(a, w.x, b.x), 0.0f), k0, k1, (uint32_t)(e4 + 0));
    float v1 = apply_dropout(fmaxf(fmaf(a, w.y, b.y), 0.0f), k0, k1, (uint32_t)(e4 + 1));
    float v2 = apply_dropout(fmaxf(fmaf(a, w.z, b.z), 0.0f), k0, k1, (uint32_t)(e4 + 2));
    float v3 = apply_dropout(fmaxf(fmaf(a, w.w, b.w), 0.0f), k0, k1, (uint32_t)(e4 + 3));
    __half2 h0 = __floats2half2_rn(v0, v1);
    __half2 h1 = __floats2half2_rn(v2, v3);
    *(uint2*)(g_h + e4) = make_uint2(*(uint32_t*)&h0, *(uint32_t*)&h1);
}

// ---------------- GEMM (HMMA): g_t = g_h @ g_wh, fp16 in, fp32 acc, fp16 out --------
// block tile 128x128, 8 warps (4m x 2n), warp tile 32x64, BK=64
__global__ void __launch_bounds__(256, 2) gemm_kernel()
{
    __shared__ __half As[128 * 72];   // row stride 72 halves (144B) — LDSM conflict-free
    __shared__ __half Bs[64 * 136];   // row stride 136 halves (272B)
    int tid = threadIdx.x;
    int m0 = blockIdx.x * 128;
    int n0 = blockIdx.y * 128;
    int warp = tid >> 5, lane = tid & 31;
    int wm = warp & 3, wn = warp >> 2;

    float acc[2][8][4];
#pragma unroll
    for (int mt = 0; mt < 2; ++mt)
#pragma unroll
        for (int nt = 0; nt < 8; ++nt)
#pragma unroll
            for (int q = 0; q < 4; ++q) acc[mt][nt][q] = 0.0f;

    uint32_t as_base = (uint32_t)__cvta_generic_to_shared(As);
    uint32_t bs_base = (uint32_t)__cvta_generic_to_shared(Bs);

    int ar = tid >> 3, ac = (tid & 7) * 8;      // A: 128x64, 4 passes of 32 rows
    int br = tid >> 4, bc = (tid & 15) * 8;     // B: 64x128, 4 passes of 16 rows

    for (int kt = 0; kt < HID; kt += 64) {
        __syncthreads();  // previous iter's LDSM done before overwrite
#pragma unroll
        for (int p = 0; p < 4; ++p) {
            uint4 v = __ldg((const uint4*)(g_h + (size_t)(m0 + ar + p * 32) * HID + kt + ac));
            *(uint4*)(As + (ar + p * 32) * 72 + ac) = v;
        }
#pragma unroll
        for (int p = 0; p < 4; ++p) {
            uint4 v = __ldg((const uint4*)(g_wh + (size_t)(kt + br + p * 16) * HID + n0 + bc));
            *(uint4*)(Bs + (br + p * 16) * 136 + bc) = v;
        }
        __syncthreads();
#pragma unroll
        for (int ks = 0; ks < 4; ++ks) {
            uint32_t a[2][4];
#pragma unroll
            for (int mt = 0; mt < 2; ++mt) {
                int row = wm * 32 + mt * 16 + (lane & 15);
                int col = ks * 16 + (lane >> 4) * 8;
                ldsm_x4(a[mt], as_base + (uint32_t)(row * 72 + col) * 2);
            }
#pragma unroll
            for (int nt = 0; nt < 8; ++nt) {
                uint32_t b[2];
                int brow = ks * 16 + (lane & 15);
                int bcol = wn * 64 + nt * 8;
                ldsm_x2_trans(b, bs_base + (uint32_t)(brow * 136 + bcol) * 2);
                mma16816(acc[0][nt], a[0], b);
                mma16816(acc[1][nt], a[1], b);
            }
        }
    }
    int g = lane >> 2, tig = lane & 3;
#pragma unroll
    for (int mt = 0; mt < 2; ++mt) {
#pragma unroll
        for (int nt = 0; nt < 8; ++nt) {
            int row = m0 + wm * 32 + mt * 16 + g;
            int col = n0 + wn * 64 + nt * 8 + tig * 2;
            __half2 h01 = __floats2half2_rn(acc[mt][nt][0], acc[mt][nt][1]);
            __half2 h23 = __floats2half2_rn(acc[mt][nt][2], acc[mt][nt][3]);
            *(__half2*)(g_t + (size_t)row * HID + col) = h01;
            *(__half2*)(g_t + (size_t)(row + 8) * HID + col) = h23;
        }
    }
}

// ---------------- aggregation + bias + relu + dropout (fused) -> g_h(fp16) ----------
__global__ void agg_kernel(const float* __restrict__ bias, uint32_t k0, uint32_t k1)
{
    int lane = threadIdx.x & 31;
    int node = (blockIdx.x * blockDim.x + threadIdx.x) >> 5;
    if (node >= N_NODES) return;
    int e = g_rowptr[node], e_end = g_rowptr[node + 1];
    float acc[8] = {0, 0, 0, 0, 0, 0, 0, 0};
    const uint4* T = (const uint4*)g_t;   // 8 halves per uint4; row = 32 uint4
    for (; e < e_end; ++e) {
        int2 sw = g_csr[e];
        float w = __int_as_float(sw.y);
        uint4 v = __ldg(T + sw.x * (HID / 8) + lane);
        float2 f0 = __half22float2(*(__half2*)&v.x);
        float2 f1 = __half22float2(*(__half2*)&v.y);
        float2 f2 = __half22float2(*(__half2*)&v.z);
        float2 f3 = __half22float2(*(__half2*)&v.w);
        acc[0] = fmaf(w, f0.x, acc[0]); acc[1] = fmaf(w, f0.y, acc[1]);
        acc[2] = fmaf(w, f1.x, acc[2]); acc[3] = fmaf(w, f1.y, acc[3]);
        acc[4] = fmaf(w, f2.x, acc[4]); acc[5] = fmaf(w, f2.y, acc[5]);
        acc[6] = fmaf(w, f3.x, acc[6]); acc[7] = fmaf(w, f3.y, acc[7]);
    }
    float di = g_dinv[node];
    {   // self loop
        uint4 v = __ldg(T + node * (HID / 8) + lane);
        float2 f0 = __half22float2(*(__half2*)&v.x);
        float2 f1 = __half22float2(*(__half2*)&v.y);
        float2 f2 = __half22float2(*(__half2*)&v.z);
        float2 f3 = __half22float2(*(__half2*)&v.w);
        acc[0] = fmaf(di, f0.x, acc[0]); acc[1] = fmaf(di, f0.y, acc[1]);
        acc[2] = fmaf(di, f1.x, acc[2]); acc[3] = fmaf(di, f1.y, acc[3]);
        acc[4] = fmaf(di, f2.x, acc[4]); acc[5] = fmaf(di, f2.y, acc[5]);
        acc[6] = fmaf(di, f3.x, acc[6]); acc[7] = fmaf(di, f3.y, acc[7]);
    }
    float4 bb0 = *(const float4*)(bias + lane * 8);
    float4 bb1 = *(const float4*)(bias + lane * 8 + 4);
    float o[8];
    o[0] = fmaxf(fmaf(acc[0], di, bb0.x), 0.0f);
    o[1] = fmaxf(fmaf(acc[1], di, bb0.y), 0.0f);
    o[2] = fmaxf(fmaf(acc[2], di, bb0.z), 0.0f);
    o[3] = fmaxf(fmaf(acc[3], di, bb0.w), 0.0f);
    o[4] = fmaxf(fmaf(acc[4], di, bb1.x), 0.0f);
    o[5] = fmaxf(fmaf(acc[5], di, bb1.y), 0.0f);
    o[6] = fmaxf(fmaf(acc[6], di, bb1.z), 0.0f);
    o[7] = fmaxf(fmaf(acc[7], di, bb1.w), 0.0f);
    uint32_t e0 = (uint32_t)(node * HID + lane * 8);
#pragma unroll
    for (int j = 0; j < 8; ++j)
        o[j] = apply_dropout(o[j], k0, k1, e0 + j);
    __half2 h0 = __floats2half2_rn(o[0], o[1]);
    __half2 h1 = __floats2half2_rn(o[2], o[3]);
    __half2 h2 = __floats2half2_rn(o[4], o[5]);
    __half2 h3 = __floats2half2_rn(o[6], o[7]);
    *(uint4*)(g_h + node * HID + lane * 8) =
        make_uint4(*(uint32_t*)&h0, *(uint32_t*)&h1, *(uint32_t*)&h2, *(uint32_t*)&h3);
}

// ---------------- per-node heads (h fp16, Wq fp32-bound) ----------------
__global__ void head_kernel(const float* __restrict__ Wq,
                            const float* __restrict__ bq,
                            float* __restrict__ out)
{
    int lane = threadIdx.x & 31;
    int node = (blockIdx.x * blockDim.x + threadIdx.x) >> 5;
    if (node >= N_NODES) return;
    const __half* hrow = g_h + node * HID;
    const float4* wrow = (const float4*)(Wq + (size_t)node * (HID * 8));
    float acc[8] = {0, 0, 0, 0, 0, 0, 0, 0};
#pragma unroll
    for (int u = 0; u < 8; ++u) {
        int hidx = u * 32 + lane;
        float s = __half2float(hrow[hidx]);
        float4 w0 = __ldg(wrow + hidx * 2);
        float4 w1 = __ldg(wrow + hidx * 2 + 1);
        acc[0] = fmaf(s, w0.x, acc[0]); acc[1] = fmaf(s, w0.y, acc[1]);
        acc[2] = fmaf(s, w0.z, acc[2]); acc[3] = fmaf(s, w0.w, acc[3]);
        acc[4] = fmaf(s, w1.x, acc[4]); acc[5] = fmaf(s, w1.y, acc[5]);
        acc[6] = fmaf(s, w1.z, acc[6]); acc[7] = fmaf(s, w1.w, acc[7]);
    }
#pragma unroll
    for (int d = 16; d; d >>= 1)
#pragma unroll
        for (int i = 0; i < 8; ++i)
            acc[i] += __shfl_xor_sync(0xffffffffu, acc[i], d);
    if (lane == 0) {
#pragma unroll
        for (int i = 0; i < 8; ++i)
            out[node * 8 + i] = acc[i] + bq[node * 8 + i];
    }
}

// ---------------- launch ----------------
extern "C" void kernel_launch(void* const* d_in, const int* in_sizes, int n_in,
                              void* d_out, int out_size)
{
    const float* x  = (const float*)d_in[0];
    const void*  ei = d_in[1];
    const float* W0 = (const float*)d_in[2];
    const float* b0 = (const float*)d_in[3];
    const float* W1 = (const float*)d_in[4];
    const float* b1 = (const float*)d_in[5];
    const float* W2 = (const float*)d_in[6];
    const float* b2 = (const float*)d_in[7];
    const float* Wq = (const float*)d_in[8];
    const float* bq = (const float*)d_in[9];
    float* out = (float*)d_out;

    uint32_t dk[3][2];
    for (uint32_t i = 0; i < 3; ++i)
        threefry2x32(0u, 42u, 0u, i, &dk[i][0], &dk[i][1]);

    detect_kernel<<<1, 32>>>((const unsigned int*)ei);
    init_kernel<<<(N_NODES + 255) / 256, 256>>>();
    convert_kernel<<<(E_EDGES + 255) / 256, 256>>>(ei);
    scan_phase1<<<NBLK, 128>>>();
    scan_phase2<<<1, 256>>>();
    scan_phase3<<<NBLK, 128>>>();
    scatter_kernel<<<(E_EDGES + 255) / 256, 256>>>(ei);

    aggx_kernel<<<(N_NODES * 32 + 255) / 256, 256>>>(x);
    expand_l1_kernel<<<(NH / 4 + 255) / 256, 256>>>(W0, b0, dk[0][0], dk[0][1]);

    convert_w_kernel<<<HID * HID / 1024, 256>>>(W1);
    gemm_kernel<<<dim3(NBLK, 2), 256>>>();
    agg_kernel<<<(N_NODES * 32 + 255) / 256, 256>>>(b1, dk[1][0], dk[1][1]);

    convert_w_kernel<<<HID * HID / 1024, 256>>>(W2);
    gemm_kernel<<<dim3(NBLK, 2), 256>>>();
    agg_kernel<<<(N_NODES * 32 + 255) / 256, 256>>>(b2, dk[2][0], dk[2][1]);

    head_kernel<<<(N_NODES * 32 + 255) / 256, 256>>>(Wq, bq, out);
}

// round 8
// speedup vs baseline: 2.2080x; 1.0656x over previous
#include <cuda_runtime.h>
#include <cuda_fp16.h>
#include <stdint.h>

#define N_NODES 20000
#define NPAD    20096           // 157 * 128
#define NBLK    157             // NPAD / 128
#define HID     256
#define E_EDGES 640000
#define NH      (N_NODES * HID) // 5,120,000

// ---------------- scratch (device globals; no allocation) ----------------
__device__ int    g_is64;
__device__ int    g_deg[N_NODES];
__device__ int    g_cursor[N_NODES];
__device__ int    g_rowptr[N_NODES + 1];
__device__ int    g_bsum[NBLK];
__device__ int2   g_csr[E_EDGES];       // (src, bitcast(dinv[src]))
__device__ float  g_dinv[N_NODES];
__device__ __half g_h[NPAD * HID];      // fp16 activations (pad rows stay zero)
__device__ __half g_t[NPAD * HID];      // fp16 GEMM output (gather payload)
__device__ __half g_wh1[HID * HID];     // fp16 weights
__device__ __half g_wh2[HID * HID];

// ---------------- mma/ldmatrix helpers ----------------
__device__ __forceinline__ void ldsm_x4(uint32_t (&r)[4], uint32_t addr)
{
    asm volatile("ldmatrix.sync.aligned.m8n8.x4.shared.b16 {%0,%1,%2,%3}, [%4];"
        : "=r"(r[0]), "=r"(r[1]), "=r"(r[2]), "=r"(r[3]) : "r"(addr));
}
__device__ __forceinline__ void ldsm_x2_trans(uint32_t (&r)[2], uint32_t addr)
{
    asm volatile("ldmatrix.sync.aligned.m8n8.x2.trans.shared.b16 {%0,%1}, [%2];"
        : "=r"(r[0]), "=r"(r[1]) : "r"(addr));
}
__device__ __forceinline__ void mma16816(float (&c)[4], const uint32_t (&a)[4], const uint32_t (&b)[2])
{
    asm volatile("mma.sync.aligned.m16n8k16.row.col.f32.f16.f16.f32 "
        "{%0,%1,%2,%3}, {%4,%5,%6,%7}, {%8,%9}, {%0,%1,%2,%3};"
        : "+f"(c[0]), "+f"(c[1]), "+f"(c[2]), "+f"(c[3])
        : "r"(a[0]), "r"(a[1]), "r"(a[2]), "r"(a[3]), "r"(b[0]), "r"(b[1]));
}

// ---------------- threefry2x32 (JAX-exact) ----------------
__host__ __device__ __forceinline__ void threefry2x32(
    uint32_t k0, uint32_t k1, uint32_t x0, uint32_t x1,
    uint32_t* o0, uint32_t* o1)
{
    uint32_t ks2 = k0 ^ k1 ^ 0x1BD11BDAu;
    x0 += k0; x1 += k1;
#define TF_R(r) { x0 += x1; x1 = (x1 << (r)) | (x1 >> (32 - (r))); x1 ^= x0; }
    TF_R(13) TF_R(15) TF_R(26) TF_R(6)
    x0 += k1; x1 += ks2 + 1u;
    TF_R(17) TF_R(29) TF_R(16) TF_R(24)
    x0 += ks2; x1 += k0 + 2u;
    TF_R(13) TF_R(15) TF_R(26) TF_R(6)
    x0 += k0; x1 += k1 + 3u;
    TF_R(17) TF_R(29) TF_R(16) TF_R(24)
    x0 += k1; x1 += ks2 + 4u;
    TF_R(13) TF_R(15) TF_R(26) TF_R(6)
    x0 += ks2; x1 += k0 + 5u;
#undef TF_R
    *o0 = x0; *o1 = x1;
}

// JAX partitionable threefry: bits32[e] = o0 ^ o1 at counter (0, e);
// keep <=> bit31 == 0; kept values scaled by 1/(1-p) = 2.
__device__ __forceinline__ float apply_dropout(float v, uint32_t k0, uint32_t k1, uint32_t e)
{
    uint32_t o0, o1;
    threefry2x32(k0, k1, 0u, e, &o0, &o1);
    return ((o0 ^ o1) & 0x80000000u) ? 0.0f : 2.0f * v;
}

// ---------------- preprocessing ----------------
__global__ void detect_kernel(const unsigned int* __restrict__ w)
{
    int lane = threadIdx.x;
    int z = (w[4 * lane + 1] == 0u) && (w[4 * lane + 3] == 0u);
    unsigned m = __ballot_sync(0xffffffffu, z);
    if (lane == 0) g_is64 = (m == 0xffffffffu);
}

__global__ void init_kernel()
{
    int i = blockIdx.x * blockDim.x + threadIdx.x;
    if (i < N_NODES) { g_deg[i] = 0; g_cursor[i] = 0; }
}

__global__ void convert_kernel(const void* __restrict__ ei)
{
    int e = blockIdx.x * blockDim.x + threadIdx.x;
    if (e >= E_EDGES) return;
    int d;
    if (g_is64) d = (int)((const long long*)ei)[E_EDGES + e];
    else        d = ((const int*)ei)[E_EDGES + e];
    atomicAdd(&g_deg[d], 1);
}

__global__ void scan_phase1()
{
    __shared__ int ws[4];
    int i = blockIdx.x * 128 + threadIdx.x;
    int v = (i < N_NODES) ? g_deg[i] : 0;
    if (i < N_NODES) g_dinv[i] = rsqrtf((float)(v + 1));  // +1 self loop
    int lane = threadIdx.x & 31, wid = threadIdx.x >> 5;
    int s = v;
#pragma unroll
    for (int d = 16; d; d >>= 1) s += __shfl_xor_sync(0xffffffffu, s, d);
    if (lane == 0) ws[wid] = s;
    __syncthreads();
    if (threadIdx.x == 0) g_bsum[blockIdx.x] = ws[0] + ws[1] + ws[2] + ws[3];
}

// local scan + own block offset computed from g_bsum (replaces phase2+phase3)
__global__ void scan_phase23()
{
    __shared__ int ws[4];
    __shared__ int s_off;
    int i = blockIdx.x * 128 + threadIdx.x;
    int v = (i < N_NODES) ? g_deg[i] : 0;
    int lane = threadIdx.x & 31, wid = threadIdx.x >> 5;

    // block offset = sum of bsum[0..blockIdx-1] (<=2 strided reads/thread)
    int part = 0;
    for (int j = threadIdx.x; j < blockIdx.x; j += 128) part += g_bsum[j];
#pragma unroll
    for (int d = 16; d; d >>= 1) part += __shfl_xor_sync(0xffffffffu, part, d);
    if (lane == 0) ws[wid] = part;
    __syncthreads();
    if (threadIdx.x == 0) s_off = ws[0] + ws[1] + ws[2] + ws[3];
    __syncthreads();
    int off = s_off;
    __syncthreads();  // ws reused below

    int s = v;
#pragma unroll
    for (int d = 1; d < 32; d <<= 1) {
        int n = __shfl_up_sync(0xffffffffu, s, d);
        if (lane >= d) s += n;
    }
    if (lane == 31) ws[wid] = s;
    __syncthreads();
    if (wid == 0 && lane < 4) {
        int w = ws[lane];
#pragma unroll
        for (int d = 1; d < 4; d <<= 1) {
            int n = __shfl_up_sync(0x0000000fu, w, d);
            if (lane >= d) w += n;
        }
        ws[lane] = w;
    }
    __syncthreads();
    if (i < N_NODES)
        g_rowptr[i] = off + (s - v) + (wid ? ws[wid - 1] : 0);
    // last block also writes total
    if (blockIdx.x == NBLK - 1 && threadIdx.x == 127)
        g_rowptr[N_NODES] = off + ws[3];
}

__global__ void scatter_kernel(const void* __restrict__ ei)
{
    int e = blockIdx.x * blockDim.x + threadIdx.x;
    if (e >= E_EDGES) return;
    int s, d;
    if (g_is64) {
        const long long* p = (const long long*)ei;
        s = (int)p[e]; d = (int)p[E_EDGES + e];
    } else {
        const int* p = (const int*)ei;
        s = p[e]; d = p[E_EDGES + e];
    }
    int pos = g_rowptr[d] + atomicAdd(&g_cursor[d], 1);
    g_csr[pos] = make_int2(s, __float_as_int(g_dinv[s]));
}

// ---------------- weights fp32 -> fp16 (both layers, one launch) ----------------
__global__ void convert_w_kernel(const float* __restrict__ W1, const float* __restrict__ W2)
{
    int i = (blockIdx.x * 256 + threadIdx.x) * 4;
    float4 v1 = *(const float4*)(W1 + i);
    float4 v2 = *(const float4*)(W2 + i);
    __half2 a1 = __floats2half2_rn(v1.x, v1.y), b1 = __floats2half2_rn(v1.z, v1.w);
    __half2 a2 = __floats2half2_rn(v2.x, v2.y), b2 = __floats2half2_rn(v2.z, v2.w);
    *(uint2*)(g_wh1 + i) = make_uint2(*(uint32_t*)&a1, *(uint32_t*)&b1);
    *(uint2*)(g_wh2 + i) = make_uint2(*(uint32_t*)&a2, *(uint32_t*)&b2);
}

// ---------------- layer 1 fused: scalar agg + expand + relu + dropout -> g_h(fp16) --
__global__ void aggx_expand_kernel(const float* __restrict__ x,
                                   const float* __restrict__ W0,
                                   const float* __restrict__ b0,
                                   uint32_t k0, uint32_t k1)
{
    int lane = threadIdx.x & 31;
    int node = (blockIdx.x * blockDim.x + threadIdx.x) >> 5;
    if (node >= N_NODES) return;
    int s = g_rowptr[node], e_end = g_rowptr[node + 1];
    float sum = 0.0f;
    for (int e = s + lane; e < e_end; e += 32) {
        int2 sw = __ldg(&g_csr[e]);
        sum = fmaf(__int_as_float(sw.y), __ldg(x + sw.x), sum);
    }
#pragma unroll
    for (int d = 16; d; d >>= 1) sum += __shfl_xor_sync(0xffffffffu, sum, d);
    float di = g_dinv[node];
    float a = di * fmaf(di, __ldg(x + node), sum);   // identical to prior aggx value

    int j = lane * 8;
    float4 w0 = *(const float4*)(W0 + j);
    float4 w1 = *(const float4*)(W0 + j + 4);
    float4 bb0 = *(const float4*)(b0 + j);
    float4 bb1 = *(const float4*)(b0 + j + 4);
    uint32_t e0 = (uint32_t)(node * HID + j);
    float v0 = apply_dropout(fmaxf(fmaf(a, w0.x, bb0.x), 0.0f), k0, k1, e0 + 0);
    float v1 = apply_dropout(fmaxf(fmaf(a, w0.y, bb0.y), 0.0f), k0, k1, e0 + 1);
    float v2 = apply_dropout(fmaxf(fmaf(a, w0.z, bb0.z), 0.0f), k0, k1, e0 + 2);
    float v3 = apply_dropout(fmaxf(fmaf(a, w0.w, bb0.w), 0.0f), k0, k1, e0 + 3);
    float v4 = apply_dropout(fmaxf(fmaf(a, w1.x, bb1.x), 0.0f), k0, k1, e0 + 4);
    float v5 = apply_dropout(fmaxf(fmaf(a, w1.y, bb1.y), 0.0f), k0, k1, e0 + 5);
    float v6 = apply_dropout(fmaxf(fmaf(a, w1.z, bb1.z), 0.0f), k0, k1, e0 + 6);
    float v7 = apply_dropout(fmaxf(fmaf(a, w1.w, bb1.w), 0.0f), k0, k1, e0 + 7);
    __half2 h0 = __floats2half2_rn(v0, v1);
    __half2 h1 = __floats2half2_rn(v2, v3);
    __half2 h2 = __floats2half2_rn(v4, v5);
    __half2 h3 = __floats2half2_rn(v6, v7);
    *(uint4*)(g_h + node * HID + j) =
        make_uint4(*(uint32_t*)&h0, *(uint32_t*)&h1, *(uint32_t*)&h2, *(uint32_t*)&h3);
}

// ---------------- GEMM (HMMA): g_t = g_h @ W, fp16 in, fp32 acc, fp16 out ----------
// block tile 128x128, 8 warps (4m x 2n), warp tile 32x64, BK=64
__global__ void __launch_bounds__(256, 2) gemm_kernel(int wsel)
{
    const __half* __restrict__ W = wsel ? g_wh2 : g_wh1;
    __shared__ __half As[128 * 72];   // row stride 72 halves (144B) — LDSM conflict-free
    __shared__ __half Bs[64 * 136];   // row stride 136 halves (272B)
    int tid = threadIdx.x;
    int m0 = blockIdx.x * 128;
    int n0 = blockIdx.y * 128;
    int warp = tid >> 5, lane = tid & 31;
    int wm = warp & 3, wn = warp >> 2;

    float acc[2][8][4];
#pragma unroll
    for (int mt = 0; mt < 2; ++mt)
#pragma unroll
        for (int nt = 0; nt < 8; ++nt)
#pragma unroll
            for (int q = 0; q < 4; ++q) acc[mt][nt][q] = 0.0f;

    uint32_t as_base = (uint32_t)__cvta_generic_to_shared(As);
    uint32_t bs_base = (uint32_t)__cvta_generic_to_shared(Bs);

    int ar = tid >> 3, ac = (tid & 7) * 8;      // A: 128x64, 4 passes of 32 rows
    int br = tid >> 4, bc = (tid & 15) * 8;     // B: 64x128, 4 passes of 16 rows

    for (int kt = 0; kt < HID; kt += 64) {
        __syncthreads();
#pragma unroll
        for (int p = 0; p < 4; ++p) {
            uint4 v = __ldg((const uint4*)(g_h + (size_t)(m0 + ar + p * 32) * HID + kt + ac));
            *(uint4*)(As + (ar + p * 32) * 72 + ac) = v;
        }
#pragma unroll
        for (int p = 0; p < 4; ++p) {
            uint4 v = __ldg((const uint4*)(W + (size_t)(kt + br + p * 16) * HID + n0 + bc));
            *(uint4*)(Bs + (br + p * 16) * 136 + bc) = v;
        }
        __syncthreads();
#pragma unroll
        for (int ks = 0; ks < 4; ++ks) {
            uint32_t a[2][4];
#pragma unroll
            for (int mt = 0; mt < 2; ++mt) {
                int row = wm * 32 + mt * 16 + (lane & 15);
                int col = ks * 16 + (lane >> 4) * 8;
                ldsm_x4(a[mt], as_base + (uint32_t)(row * 72 + col) * 2);
            }
#pragma unroll
            for (int nt = 0; nt < 8; ++nt) {
                uint32_t b[2];
                int brow = ks * 16 + (lane & 15);
                int bcol = wn * 64 + nt * 8;
                ldsm_x2_trans(b, bs_base + (uint32_t)(brow * 136 + bcol) * 2);
                mma16816(acc[0][nt], a[0], b);
                mma16816(acc[1][nt], a[1], b);
            }
        }
    }
    int g = lane >> 2, tig = lane & 3;
#pragma unroll
    for (int mt = 0; mt < 2; ++mt) {
#pragma unroll
        for (int nt = 0; nt < 8; ++nt) {
            int row = m0 + wm * 32 + mt * 16 + g;
            int col = n0 + wn * 64 + nt * 8 + tig * 2;
            __half2 h01 = __floats2half2_rn(acc[mt][nt][0], acc[mt][nt][1]);
            __half2 h23 = __floats2half2_rn(acc[mt][nt][2], acc[mt][nt][3]);
            *(__half2*)(g_t + (size_t)row * HID + col) = h01;
            *(__half2*)(g_t + (size_t)(row + 8) * HID + col) = h23;
        }
    }
}

// ---------------- aggregation + bias + relu + dropout (fused) -> g_h(fp16) ----------
// 1-deep software prefetch of CSR entry + row (MLP 2)
__global__ void agg_kernel(const float* __restrict__ bias, uint32_t k0, uint32_t k1)
{
    int lane = threadIdx.x & 31;
    int node = (blockIdx.x * blockDim.x + threadIdx.x) >> 5;
    if (node >= N_NODES) return;
    int e = g_rowptr[node], e_end = g_rowptr[node + 1];
    float acc[8] = {0, 0, 0, 0, 0, 0, 0, 0};
    const uint4* T = (const uint4*)g_t;   // 8 halves per uint4; row = 32 uint4

    if (e < e_end) {
        int2 sw = __ldg(&g_csr[e]);
        uint4 v = __ldg(T + sw.x * (HID / 8) + lane);
        while (++e < e_end) {
            int2 sw_n = __ldg(&g_csr[e]);
            uint4 v_n = __ldg(T + sw_n.x * (HID / 8) + lane);
            float w = __int_as_float(sw.y);
            float2 f0 = __half22float2(*(__half2*)&v.x);
            float2 f1 = __half22float2(*(__half2*)&v.y);
            float2 f2 = __half22float2(*(__half2*)&v.z);
            float2 f3 = __half22float2(*(__half2*)&v.w);
            acc[0] = fmaf(w, f0.x, acc[0]); acc[1] = fmaf(w, f0.y, acc[1]);
            acc[2] = fmaf(w, f1.x, acc[2]); acc[3] = fmaf(w, f1.y, acc[3]);
            acc[4] = fmaf(w, f2.x, acc[4]); acc[5] = fmaf(w, f2.y, acc[5]);
            acc[6] = fmaf(w, f3.x, acc[6]); acc[7] = fmaf(w, f3.y, acc[7]);
            sw = sw_n; v = v_n;
        }
        float w = __int_as_float(sw.y);
        float2 f0 = __half22float2(*(__half2*)&v.x);
        float2 f1 = __half22float2(*(__half2*)&v.y);
        float2 f2 = __half22float2(*(__half2*)&v.z);
        float2 f3 = __half22float2(*(__half2*)&v.w);
        acc[0] = fmaf(w, f0.x, acc[0]); acc[1] = fmaf(w, f0.y, acc[1]);
        acc[2] = fmaf(w, f1.x, acc[2]); acc[3] = fmaf(w, f1.y, acc[3]);
        acc[4] = fmaf(w, f2.x, acc[4]); acc[5] = fmaf(w, f2.y, acc[5]);
        acc[6] = fmaf(w, f3.x, acc[6]); acc[7] = fmaf(w, f3.y, acc[7]);
    }
    float di = g_dinv[node];
    {   // self loop
        uint4 v = __ldg(T + node * (HID / 8) + lane);
        float2 f0 = __half22float2(*(__half2*)&v.x);
        float2 f1 = __half22float2(*(__half2*)&v.y);
        float2 f2 = __half22float2(*(__half2*)&v.z);
        float2 f3 = __half22float2(*(__half2*)&v.w);
        acc[0] = fmaf(di, f0.x, acc[0]); acc[1] = fmaf(di, f0.y, acc[1]);
        acc[2] = fmaf(di, f1.x, acc[2]); acc[3] = fmaf(di, f1.y, acc[3]);
        acc[4] = fmaf(di, f2.x, acc[4]); acc[5] = fmaf(di, f2.y, acc[5]);
        acc[6] = fmaf(di, f3.x, acc[6]); acc[7] = fmaf(di, f3.y, acc[7]);
    }
    float4 bb0 = *(const float4*)(bias + lane * 8);
    float4 bb1 = *(const float4*)(bias + lane * 8 + 4);
    float o[8];
    o[0] = fmaxf(fmaf(acc[0], di, bb0.x), 0.0f);
    o[1] = fmaxf(fmaf(acc[1], di, bb0.y), 0.0f);
    o[2] = fmaxf(fmaf(acc[2], di, bb0.z), 0.0f);
    o[3] = fmaxf(fmaf(acc[3], di, bb0.w), 0.0f);
    o[4] = fmaxf(fmaf(acc[4], di, bb1.x), 0.0f);
    o[5] = fmaxf(fmaf(acc[5], di, bb1.y), 0.0f);
    o[6] = fmaxf(fmaf(acc[6], di, bb1.z), 0.0f);
    o[7] = fmaxf(fmaf(acc[7], di, bb1.w), 0.0f);
    uint32_t e0 = (uint32_t)(node * HID + lane * 8);
#pragma unroll
    for (int j = 0; j < 8; ++j)
        o[j] = apply_dropout(o[j], k0, k1, e0 + j);
    __half2 h0 = __floats2half2_rn(o[0], o[1]);
    __half2 h1 = __floats2half2_rn(o[2], o[3]);
    __half2 h2 = __floats2half2_rn(o[4], o[5]);
    __half2 h3 = __floats2half2_rn(o[6], o[7]);
    *(uint4*)(g_h + node * HID + lane * 8) =
        make_uint4(*(uint32_t*)&h0, *(uint32_t*)&h1, *(uint32_t*)&h2, *(uint32_t*)&h3);
}

// ---------------- per-node heads (h fp16, Wq fp32-bound) ----------------
__global__ void head_kernel(const float* __restrict__ Wq,
                            const float* __restrict__ bq,
                            float* __restrict__ out)
{
    int lane = threadIdx.x & 31;
    int node = (blockIdx.x * blockDim.x + threadIdx.x) >> 5;
    if (node >= N_NODES) return;
    const __half* hrow = g_h + node * HID;
    const float4* wrow = (const float4*)(Wq + (size_t)node * (HID * 8));
    float acc[8] = {0, 0, 0, 0, 0, 0, 0, 0};
#pragma unroll
    for (int u = 0; u < 8; ++u) {
        int hidx = u * 32 + lane;
        float s = __half2float(hrow[hidx]);
        float4 w0 = __ldg(wrow + hidx * 2);
        float4 w1 = __ldg(wrow + hidx * 2 + 1);
        acc[0] = fmaf(s, w0.x, acc[0]); acc[1] = fmaf(s, w0.y, acc[1]);
        acc[2] = fmaf(s, w0.z, acc[2]); acc[3] = fmaf(s, w0.w, acc[3]);
        acc[4] = fmaf(s, w1.x, acc[4]); acc[5] = fmaf(s, w1.y, acc[5]);
        acc[6] = fmaf(s, w1.z, acc[6]); acc[7] = fmaf(s, w1.w, acc[7]);
    }
#pragma unroll
    for (int d = 16; d; d >>= 1)
#pragma unroll
        for (int i = 0; i < 8; ++i)
            acc[i] += __shfl_xor_sync(0xffffffffu, acc[i], d);
    if (lane == 0) {
#pragma unroll
        for (int i = 0; i < 8; ++i)
            out[node * 8 + i] = acc[i] + bq[node * 8 + i];
    }
}

// ---------------- launch ----------------
extern "C" void kernel_launch(void* const* d_in, const int* in_sizes, int n_in,
                              void* d_out, int out_size)
{
    const float* x  = (const float*)d_in[0];
    const void*  ei = d_in[1];
    const float* W0 = (const float*)d_in[2];
    const float* b0 = (const float*)d_in[3];
    const float* W1 = (const float*)d_in[4];
    const float* b1 = (const float*)d_in[5];
    const float* W2 = (const float*)d_in[6];
    const float* b2 = (const float*)d_in[7];
    const float* Wq = (const float*)d_in[8];
    const float* bq = (const float*)d_in[9];
    float* out = (float*)d_out;

    uint32_t dk[3][2];
    for (uint32_t i = 0; i < 3; ++i)
        threefry2x32(0u, 42u, 0u, i, &dk[i][0], &dk[i][1]);

    detect_kernel<<<1, 32>>>((const unsigned int*)ei);
    init_kernel<<<(N_NODES + 255) / 256, 256>>>();
    convert_w_kernel<<<HID * HID / 1024, 256>>>(W1, W2);
    convert_kernel<<<(E_EDGES + 255) / 256, 256>>>(ei);
    scan_phase1<<<NBLK, 128>>>();
    scan_phase23<<<NBLK, 128>>>();
    scatter_kernel<<<(E_EDGES + 255) / 256, 256>>>(ei);

    aggx_expand_kernel<<<(N_NODES * 32 + 255) / 256, 256>>>(x, W0, b0, dk[0][0], dk[0][1]);

    gemm_kernel<<<dim3(NBLK, 2), 256>>>(0);
    agg_kernel<<<(N_NODES * 32 + 255) / 256, 256>>>(b1, dk[1][0], dk[1][1]);

    gemm_kernel<<<dim3(NBLK, 2), 256>>>(1);
    agg_kernel<<<(N_NODES * 32 + 255) / 256, 256>>>(b2, dk[2][0], dk[2][1]);

    head_kernel<<<(N_NODES * 32 + 255) / 256, 256>>>(Wq, bq, out);
}

// round 9
// speedup vs baseline: 2.2485x; 1.0183x over previous
#include <cuda_runtime.h>
#include <cuda_fp16.h>
#include <stdint.h>

#define N_NODES 20000
#define NPAD    20096           // 157 * 128
#define NBLK    157             // NPAD / 128
#define HID     256
#define E_EDGES 640000
#define NH      (N_NODES * HID) // 5,120,000

// ---------------- scratch (device globals; no allocation) ----------------
__device__ int    g_is64;
__device__ int    g_deg[N_NODES];
__device__ int    g_cursor[N_NODES];
__device__ int    g_rowptr[N_NODES + 1];
__device__ int    g_bsum[NBLK];
__device__ int2   g_csr[E_EDGES];       // (src, bitcast(dinv[src]))
__device__ float  g_dinv[N_NODES];
__device__ __half g_h[NPAD * HID];      // fp16 activations (pad rows stay zero)
__device__ __half g_t[NPAD * HID];      // fp16 GEMM output (gather payload)
__device__ __half g_wh1[HID * HID];     // fp16 weights
__device__ __half g_wh2[HID * HID];

// ---------------- mma/ldmatrix helpers ----------------
__device__ __forceinline__ void ldsm_x4(uint32_t (&r)[4], uint32_t addr)
{
    asm volatile("ldmatrix.sync.aligned.m8n8.x4.shared.b16 {%0,%1,%2,%3}, [%4];"
        : "=r"(r[0]), "=r"(r[1]), "=r"(r[2]), "=r"(r[3]) : "r"(addr));
}
__device__ __forceinline__ void ldsm_x2_trans(uint32_t (&r)[2], uint32_t addr)
{
    asm volatile("ldmatrix.sync.aligned.m8n8.x2.trans.shared.b16 {%0,%1}, [%2];"
        : "=r"(r[0]), "=r"(r[1]) : "r"(addr));
}
__device__ __forceinline__ void mma16816(float (&c)[4], const uint32_t (&a)[4], const uint32_t (&b)[2])
{
    asm volatile("mma.sync.aligned.m16n8k16.row.col.f32.f16.f16.f32 "
        "{%0,%1,%2,%3}, {%4,%5,%6,%7}, {%8,%9}, {%0,%1,%2,%3};"
        : "+f"(c[0]), "+f"(c[1]), "+f"(c[2]), "+f"(c[3])
        : "r"(a[0]), "r"(a[1]), "r"(a[2]), "r"(a[3]), "r"(b[0]), "r"(b[1]));
}

// ---------------- threefry2x32 (JAX-exact) ----------------
__host__ __device__ __forceinline__ void threefry2x32(
    uint32_t k0, uint32_t k1, uint32_t x0, uint32_t x1,
    uint32_t* o0, uint32_t* o1)
{
    uint32_t ks2 = k0 ^ k1 ^ 0x1BD11BDAu;
    x0 += k0; x1 += k1;
#define TF_R(r) { x0 += x1; x1 = (x1 << (r)) | (x1 >> (32 - (r))); x1 ^= x0; }
    TF_R(13) TF_R(15) TF_R(26) TF_R(6)
    x0 += k1; x1 += ks2 + 1u;
    TF_R(17) TF_R(29) TF_R(16) TF_R(24)
    x0 += ks2; x1 += k0 + 2u;
    TF_R(13) TF_R(15) TF_R(26) TF_R(6)
    x0 += k0; x1 += k1 + 3u;
    TF_R(17) TF_R(29) TF_R(16) TF_R(24)
    x0 += k1; x1 += ks2 + 4u;
    TF_R(13) TF_R(15) TF_R(26) TF_R(6)
    x0 += ks2; x1 += k0 + 5u;
#undef TF_R
    *o0 = x0; *o1 = x1;
}

// JAX partitionable threefry: bits32[e] = o0 ^ o1 at counter (0, e);
// keep <=> bit31 == 0; kept values scaled by 1/(1-p) = 2.
__device__ __forceinline__ float apply_dropout(float v, uint32_t k0, uint32_t k1, uint32_t e)
{
    uint32_t o0, o1;
    threefry2x32(k0, k1, 0u, e, &o0, &o1);
    return ((o0 ^ o1) & 0x80000000u) ? 0.0f : 2.0f * v;
}

// ---------------- prep: detect dtype + zero deg/cursor + convert weights ----------
// blocks [0,79): init; block 79: detect; blocks [80,144): convert_w
__global__ void prep_kernel(const unsigned int* __restrict__ w,
                            const float* __restrict__ W1,
                            const float* __restrict__ W2)
{
    int b = blockIdx.x;
    if (b < 79) {
        int i = b * 256 + threadIdx.x;
        if (i < N_NODES) { g_deg[i] = 0; g_cursor[i] = 0; }
    } else if (b == 79) {
        if (threadIdx.x < 32) {
            int lane = threadIdx.x;
            int z = (w[4 * lane + 1] == 0u) && (w[4 * lane + 3] == 0u);
            unsigned m = __ballot_sync(0xffffffffu, z);
            if (lane == 0) g_is64 = (m == 0xffffffffu);
        }
    } else {
        int i = ((b - 80) * 256 + threadIdx.x) * 4;
        float4 v1 = *(const float4*)(W1 + i);
        float4 v2 = *(const float4*)(W2 + i);
        __half2 a1 = __floats2half2_rn(v1.x, v1.y), b1 = __floats2half2_rn(v1.z, v1.w);
        __half2 a2 = __floats2half2_rn(v2.x, v2.y), b2 = __floats2half2_rn(v2.z, v2.w);
        *(uint2*)(g_wh1 + i) = make_uint2(*(uint32_t*)&a1, *(uint32_t*)&b1);
        *(uint2*)(g_wh2 + i) = make_uint2(*(uint32_t*)&a2, *(uint32_t*)&b2);
    }
}

__global__ void convert_kernel(const void* __restrict__ ei)
{
    int e = blockIdx.x * blockDim.x + threadIdx.x;
    if (e >= E_EDGES) return;
    int d;
    if (g_is64) d = (int)((const long long*)ei)[E_EDGES + e];
    else        d = ((const int*)ei)[E_EDGES + e];
    atomicAdd(&g_deg[d], 1);
}

__global__ void scan_phase1()
{
    __shared__ int ws[4];
    int i = blockIdx.x * 128 + threadIdx.x;
    int v = (i < N_NODES) ? g_deg[i] : 0;
    if (i < N_NODES) g_dinv[i] = rsqrtf((float)(v + 1));  // +1 self loop
    int lane = threadIdx.x & 31, wid = threadIdx.x >> 5;
    int s = v;
#pragma unroll
    for (int d = 16; d; d >>= 1) s += __shfl_xor_sync(0xffffffffu, s, d);
    if (lane == 0) ws[wid] = s;
    __syncthreads();
    if (threadIdx.x == 0) g_bsum[blockIdx.x] = ws[0] + ws[1] + ws[2] + ws[3];
}

// local scan + own block offset computed from g_bsum
__global__ void scan_phase23()
{
    __shared__ int ws[4];
    __shared__ int s_off;
    int i = blockIdx.x * 128 + threadIdx.x;
    int v = (i < N_NODES) ? g_deg[i] : 0;
    int lane = threadIdx.x & 31, wid = threadIdx.x >> 5;

    int part = 0;
    for (int j = threadIdx.x; j < blockIdx.x; j += 128) part += g_bsum[j];
#pragma unroll
    for (int d = 16; d; d >>= 1) part += __shfl_xor_sync(0xffffffffu, part, d);
    if (lane == 0) ws[wid] = part;
    __syncthreads();
    if (threadIdx.x == 0) s_off = ws[0] + ws[1] + ws[2] + ws[3];
    __syncthreads();
    int off = s_off;
    __syncthreads();  // ws reused below

    int s = v;
#pragma unroll
    for (int d = 1; d < 32; d <<= 1) {
        int n = __shfl_up_sync(0xffffffffu, s, d);
        if (lane >= d) s += n;
    }
    if (lane == 31) ws[wid] = s;
    __syncthreads();
    if (wid == 0 && lane < 4) {
        int w = ws[lane];
#pragma unroll
        for (int d = 1; d < 4; d <<= 1) {
            int n = __shfl_up_sync(0x0000000fu, w, d);
            if (lane >= d) w += n;
        }
        ws[lane] = w;
    }
    __syncthreads();
    if (i < N_NODES)
        g_rowptr[i] = off + (s - v) + (wid ? ws[wid - 1] : 0);
    if (blockIdx.x == NBLK - 1 && threadIdx.x == 127)
        g_rowptr[N_NODES] = off + ws[3];
}

__global__ void scatter_kernel(const void* __restrict__ ei)
{
    int e = blockIdx.x * blockDim.x + threadIdx.x;
    if (e >= E_EDGES) return;
    int s, d;
    if (g_is64) {
        const long long* p = (const long long*)ei;
        s = (int)p[e]; d = (int)p[E_EDGES + e];
    } else {
        const int* p = (const int*)ei;
        s = p[e]; d = p[E_EDGES + e];
    }
    int pos = g_rowptr[d] + atomicAdd(&g_cursor[d], 1);
    g_csr[pos] = make_int2(s, __float_as_int(g_dinv[s]));
}

// ---------------- layer 1 fused: scalar agg + expand + relu + dropout -> g_h(fp16) --
__global__ void aggx_expand_kernel(const float* __restrict__ x,
                                   const float* __restrict__ W0,
                                   const float* __restrict__ b0,
                                   uint32_t k0, uint32_t k1)
{
    int lane = threadIdx.x & 31;
    int node = (blockIdx.x * blockDim.x + threadIdx.x) >> 5;
    if (node >= N_NODES) return;
    int s = g_rowptr[node], e_end = g_rowptr[node + 1];
    float sum = 0.0f;
    for (int e = s + lane; e < e_end; e += 32) {
        int2 sw = __ldg(&g_csr[e]);
        sum = fmaf(__int_as_float(sw.y), __ldg(x + sw.x), sum);
    }
#pragma unroll
    for (int d = 16; d; d >>= 1) sum += __shfl_xor_sync(0xffffffffu, sum, d);
    float di = g_dinv[node];
    float a = di * fmaf(di, __ldg(x + node), sum);

    int j = lane * 8;
    float4 w0 = *(const float4*)(W0 + j);
    float4 w1 = *(const float4*)(W0 + j + 4);
    float4 bb0 = *(const float4*)(b0 + j);
    float4 bb1 = *(const float4*)(b0 + j + 4);
    uint32_t e0 = (uint32_t)(node * HID + j);
    float v0 = apply_dropout(fmaxf(fmaf(a, w0.x, bb0.x), 0.0f), k0, k1, e0 + 0);
    float v1 = apply_dropout(fmaxf(fmaf(a, w0.y, bb0.y), 0.0f), k0, k1, e0 + 1);
    float v2 = apply_dropout(fmaxf(fmaf(a, w0.z, bb0.z), 0.0f), k0, k1, e0 + 2);
    float v3 = apply_dropout(fmaxf(fmaf(a, w0.w, bb0.w), 0.0f), k0, k1, e0 + 3);
    float v4 = apply_dropout(fmaxf(fmaf(a, w1.x, bb1.x), 0.0f), k0, k1, e0 + 4);
    float v5 = apply_dropout(fmaxf(fmaf(a, w1.y, bb1.y), 0.0f), k0, k1, e0 + 5);
    float v6 = apply_dropout(fmaxf(fmaf(a, w1.z, bb1.z), 0.0f), k0, k1, e0 + 6);
    float v7 = apply_dropout(fmaxf(fmaf(a, w1.w, bb1.w), 0.0f), k0, k1, e0 + 7);
    __half2 h0 = __floats2half2_rn(v0, v1);
    __half2 h1 = __floats2half2_rn(v2, v3);
    __half2 h2 = __floats2half2_rn(v4, v5);
    __half2 h3 = __floats2half2_rn(v6, v7);
    *(uint4*)(g_h + node * HID + j) =
        make_uint4(*(uint32_t*)&h0, *(uint32_t*)&h1, *(uint32_t*)&h2, *(uint32_t*)&h3);
}

// ---------------- GEMM (HMMA): g_t = g_h @ W, fp16 in, fp32 acc, fp16 out ----------
__global__ void __launch_bounds__(256, 2) gemm_kernel(int wsel)
{
    const __half* __restrict__ W = wsel ? g_wh2 : g_wh1;
    __shared__ __half As[128 * 72];
    __shared__ __half Bs[64 * 136];
    int tid = threadIdx.x;
    int m0 = blockIdx.x * 128;
    int n0 = blockIdx.y * 128;
    int warp = tid >> 5, lane = tid & 31;
    int wm = warp & 3, wn = warp >> 2;

    float acc[2][8][4];
#pragma unroll
    for (int mt = 0; mt < 2; ++mt)
#pragma unroll
        for (int nt = 0; nt < 8; ++nt)
#pragma unroll
            for (int q = 0; q < 4; ++q) acc[mt][nt][q] = 0.0f;

    uint32_t as_base = (uint32_t)__cvta_generic_to_shared(As);
    uint32_t bs_base = (uint32_t)__cvta_generic_to_shared(Bs);

    int ar = tid >> 3, ac = (tid & 7) * 8;
    int br = tid >> 4, bc = (tid & 15) * 8;

    for (int kt = 0; kt < HID; kt += 64) {
        __syncthreads();
#pragma unroll
        for (int p = 0; p < 4; ++p) {
            uint4 v = __ldg((const uint4*)(g_h + (size_t)(m0 + ar + p * 32) * HID + kt + ac));
            *(uint4*)(As + (ar + p * 32) * 72 + ac) = v;
        }
#pragma unroll
        for (int p = 0; p < 4; ++p) {
            uint4 v = __ldg((const uint4*)(W + (size_t)(kt + br + p * 16) * HID + n0 + bc));
            *(uint4*)(Bs + (br + p * 16) * 136 + bc) = v;
        }
        __syncthreads();
#pragma unroll
        for (int ks = 0; ks < 4; ++ks) {
            uint32_t a[2][4];
#pragma unroll
            for (int mt = 0; mt < 2; ++mt) {
                int row = wm * 32 + mt * 16 + (lane & 15);
                int col = ks * 16 + (lane >> 4) * 8;
                ldsm_x4(a[mt], as_base + (uint32_t)(row * 72 + col) * 2);
            }
#pragma unroll
            for (int nt = 0; nt < 8; ++nt) {
                uint32_t b[2];
                int brow = ks * 16 + (lane & 15);
                int bcol = wn * 64 + nt * 8;
                ldsm_x2_trans(b, bs_base + (uint32_t)(brow * 136 + bcol) * 2);
                mma16816(acc[0][nt], a[0], b);
                mma16816(acc[1][nt], a[1], b);
            }
        }
    }
    int g = lane >> 2, tig = lane & 3;
#pragma unroll
    for (int mt = 0; mt < 2; ++mt) {
#pragma unroll
        for (int nt = 0; nt < 8; ++nt) {
            int row = m0 + wm * 32 + mt * 16 + g;
            int col = n0 + wn * 64 + nt * 8 + tig * 2;
            __half2 h01 = __floats2half2_rn(acc[mt][nt][0], acc[mt][nt][1]);
            __half2 h23 = __floats2half2_rn(acc[mt][nt][2], acc[mt][nt][3]);
            *(__half2*)(g_t + (size_t)row * HID + col) = h01;
            *(__half2*)(g_t + (size_t)(row + 8) * HID + col) = h23;
        }
    }
}

// ---------------- shared agg core: gather + bias + relu + dropout -> o[8] ----------
__device__ __forceinline__ void agg_core(int node, int lane,
                                         const float* __restrict__ bias,
                                         uint32_t k0, uint32_t k1, float (&o)[8])
{
    int e = g_rowptr[node], e_end = g_rowptr[node + 1];
    float acc[8] = {0, 0, 0, 0, 0, 0, 0, 0};
    const uint4* T = (const uint4*)g_t;
    if (e < e_end) {
        int2 sw = __ldg(&g_csr[e]);
        uint4 v = __ldg(T + sw.x * (HID / 8) + lane);
        while (++e < e_end) {
            int2 sw_n = __ldg(&g_csr[e]);
            uint4 v_n = __ldg(T + sw_n.x * (HID / 8) + lane);
            float w = __int_as_float(sw.y);
            float2 f0 = __half22float2(*(__half2*)&v.x);
            float2 f1 = __half22float2(*(__half2*)&v.y);
            float2 f2 = __half22float2(*(__half2*)&v.z);
            float2 f3 = __half22float2(*(__half2*)&v.w);
            acc[0] = fmaf(w, f0.x, acc[0]); acc[1] = fmaf(w, f0.y, acc[1]);
            acc[2] = fmaf(w, f1.x, acc[2]); acc[3] = fmaf(w, f1.y, acc[3]);
            acc[4] = fmaf(w, f2.x, acc[4]); acc[5] = fmaf(w, f2.y, acc[5]);
            acc[6] = fmaf(w, f3.x, acc[6]); acc[7] = fmaf(w, f3.y, acc[7]);
            sw = sw_n; v = v_n;
        }
        float w = __int_as_float(sw.y);
        float2 f0 = __half22float2(*(__half2*)&v.x);
        float2 f1 = __half22float2(*(__half2*)&v.y);
        float2 f2 = __half22float2(*(__half2*)&v.z);
        float2 f3 = __half22float2(*(__half2*)&v.w);
        acc[0] = fmaf(w, f0.x, acc[0]); acc[1] = fmaf(w, f0.y, acc[1]);
        acc[2] = fmaf(w, f1.x, acc[2]); acc[3] = fmaf(w, f1.y, acc[3]);
        acc[4] = fmaf(w, f2.x, acc[4]); acc[5] = fmaf(w, f2.y, acc[5]);
        acc[6] = fmaf(w, f3.x, acc[6]); acc[7] = fmaf(w, f3.y, acc[7]);
    }
    float di = g_dinv[node];
    {   // self loop
        uint4 v = __ldg(T + node * (HID / 8) + lane);
        float2 f0 = __half22float2(*(__half2*)&v.x);
        float2 f1 = __half22float2(*(__half2*)&v.y);
        float2 f2 = __half22float2(*(__half2*)&v.z);
        float2 f3 = __half22float2(*(__half2*)&v.w);
        acc[0] = fmaf(di, f0.x, acc[0]); acc[1] = fmaf(di, f0.y, acc[1]);
        acc[2] = fmaf(di, f1.x, acc[2]); acc[3] = fmaf(di, f1.y, acc[3]);
        acc[4] = fmaf(di, f2.x, acc[4]); acc[5] = fmaf(di, f2.y, acc[5]);
        acc[6] = fmaf(di, f3.x, acc[6]); acc[7] = fmaf(di, f3.y, acc[7]);
    }
    float4 bb0 = *(const float4*)(bias + lane * 8);
    float4 bb1 = *(const float4*)(bias + lane * 8 + 4);
    o[0] = fmaxf(fmaf(acc[0], di, bb0.x), 0.0f);
    o[1] = fmaxf(fmaf(acc[1], di, bb0.y), 0.0f);
    o[2] = fmaxf(fmaf(acc[2], di, bb0.z), 0.0f);
    o[3] = fmaxf(fmaf(acc[3], di, bb0.w), 0.0f);
    o[4] = fmaxf(fmaf(acc[4], di, bb1.x), 0.0f);
    o[5] = fmaxf(fmaf(acc[5], di, bb1.y), 0.0f);
    o[6] = fmaxf(fmaf(acc[6], di, bb1.z), 0.0f);
    o[7] = fmaxf(fmaf(acc[7], di, bb1.w), 0.0f);
    uint32_t e0 = (uint32_t)(node * HID + lane * 8);
#pragma unroll
    for (int j = 0; j < 8; ++j)
        o[j] = apply_dropout(o[j], k0, k1, e0 + j);
}

// layer 2: agg -> g_h (fp16)
__global__ void agg_kernel(const float* __restrict__ bias, uint32_t k0, uint32_t k1)
{
    int lane = threadIdx.x & 31;
    int node = (blockIdx.x * blockDim.x + threadIdx.x) >> 5;
    if (node >= N_NODES) return;
    float o[8];
    agg_core(node, lane, bias, k0, k1, o);
    __half2 h0 = __floats2half2_rn(o[0], o[1]);
    __half2 h1 = __floats2half2_rn(o[2], o[3]);
    __half2 h2 = __floats2half2_rn(o[4], o[5]);
    __half2 h3 = __floats2half2_rn(o[6], o[7]);
    *(uint4*)(g_h + node * HID + lane * 8) =
        make_uint4(*(uint32_t*)&h0, *(uint32_t*)&h1, *(uint32_t*)&h2, *(uint32_t*)&h3);
}

// layer 3 fused with heads: agg -> q = h @ Wq[node] + bq[node] -> out
// lane owns channels lane*8..lane*8+7; reads its 256B Wq slice contiguously
__global__ void agg_head_kernel(const float* __restrict__ bias, uint32_t k0, uint32_t k1,
                                const float* __restrict__ Wq,
                                const float* __restrict__ bq,
                                float* __restrict__ out)
{
    int lane = threadIdx.x & 31;
    int node = (blockIdx.x * blockDim.x + threadIdx.x) >> 5;
    if (node >= N_NODES) return;
    float o[8];
    agg_core(node, lane, bias, k0, k1, o);

    const float4* wrow = (const float4*)(Wq + (size_t)node * (HID * 8) + lane * 64);
    float q[8] = {0, 0, 0, 0, 0, 0, 0, 0};
#pragma unroll
    for (int j = 0; j < 8; ++j) {
        float s = o[j];
        float4 w0 = __ldg(wrow + j * 2);
        float4 w1 = __ldg(wrow + j * 2 + 1);
        q[0] = fmaf(s, w0.x, q[0]); q[1] = fmaf(s, w0.y, q[1]);
        q[2] = fmaf(s, w0.z, q[2]); q[3] = fmaf(s, w0.w, q[3]);
        q[4] = fmaf(s, w1.x, q[4]); q[5] = fmaf(s, w1.y, q[5]);
        q[6] = fmaf(s, w1.z, q[6]); q[7] = fmaf(s, w1.w, q[7]);
    }
#pragma unroll
    for (int d = 16; d; d >>= 1)
#pragma unroll
        for (int i = 0; i < 8; ++i)
            q[i] += __shfl_xor_sync(0xffffffffu, q[i], d);
    if (lane == 0) {
#pragma unroll
        for (int i = 0; i < 8; ++i)
            out[node * 8 + i] = q[i] + bq[node * 8 + i];
    }
}

// ---------------- launch ----------------
extern "C" void kernel_launch(void* const* d_in, const int* in_sizes, int n_in,
                              void* d_out, int out_size)
{
    const float* x  = (const float*)d_in[0];
    const void*  ei = d_in[1];
    const float* W0 = (const float*)d_in[2];
    const float* b0 = (const float*)d_in[3];
    const float* W1 = (const float*)d_in[4];
    const float* b1 = (const float*)d_in[5];
    const float* W2 = (const float*)d_in[6];
    const float* b2 = (const float*)d_in[7];
    const float* Wq = (const float*)d_in[8];
    const float* bq = (const float*)d_in[9];
    float* out = (float*)d_out;

    uint32_t dk[3][2];
    for (uint32_t i = 0; i < 3; ++i)
        threefry2x32(0u, 42u, 0u, i, &dk[i][0], &dk[i][1]);

    prep_kernel<<<144, 256>>>((const unsigned int*)ei, W1, W2);
    convert_kernel<<<(E_EDGES + 255) / 256, 256>>>(ei);
    scan_phase1<<<NBLK, 128>>>();
    scan_phase23<<<NBLK, 128>>>();
    scatter_kernel<<<(E_EDGES + 255) / 256, 256>>>(ei);

    aggx_expand_kernel<<<(N_NODES * 32 + 255) / 256, 256>>>(x, W0, b0, dk[0][0], dk[0][1]);

    gemm_kernel<<<dim3(NBLK, 2), 256>>>(0);
    agg_kernel<<<(N_NODES * 32 + 255) / 256, 256>>>(b1, dk[1][0], dk[1][1]);

    gemm_kernel<<<dim3(NBLK, 2), 256>>>(1);
    agg_head_kernel<<<(N_NODES * 32 + 255) / 256, 256>>>(b2, dk[2][0], dk[2][1], Wq, bq, out);
}